// round 1
// baseline (speedup 1.0000x reference)
#include <cuda_runtime.h>
#include <math.h>

#define NN 10000
#define NE 200000
#define NT 400000
#define NORB 9
#define HD 128
#define CFD 64
#define CD 32

// ---------------- scratch (device globals; no allocation allowed) ----------
__device__ float g_h[NN * 64];                   // node MLP out: xh=[0:32), xk=[32:64)
__device__ float g_cji_c[(size_t)NE * NORB * CD]; // 230.4 MB
__device__ float g_ckj_n[(size_t)NE * NORB * CD]; // 230.4 MB (pre-normalized ckj)
__device__ float g_rbw[NE * NORB];
__device__ float g_agg[(size_t)NE * CD];
__device__ float g_tbw[(size_t)NE * CD];
__device__ float g_acc[NN * CD];

__device__ __forceinline__ float sigm(float x) { return 1.f / (1.f + __expf(-x)); }
__device__ __forceinline__ float silu(float x) { return x * sigm(x); }

__device__ __forceinline__ float warp_sum(float s) {
#pragma unroll
    for (int off = 16; off; off >>= 1) s += __shfl_xor_sync(0xffffffffu, s, off);
    return s;
}

// ---------------- K0: zero accumulators + rb_w = rb * cutoff_w -------------
__global__ void k0_init(const float* __restrict__ rb, const float* __restrict__ cw) {
    int i = blockIdx.x * blockDim.x + threadIdx.x;
    if (i < NE * CD) g_agg[i] = 0.f;
    if (i < NN * CD) g_acc[i] = 0.f;
    if (i < NE * NORB) g_rbw[i] = rb[i] * cw[i / NORB];
}

// ---------------- K1: h = x @ W1^T + b1 ------------------------------------
__global__ void __launch_bounds__(256) k1_node(const float* __restrict__ x,
                                               const float* __restrict__ W1,
                                               const float* __restrict__ b1) {
    __shared__ float sW[HD * 64];   // transposed [k][o]
    __shared__ float sx[4][HD];
    int tid = threadIdx.x;
    for (int idx = tid; idx < 64 * HD; idx += 256) {
        int o = idx / HD, k = idx % HD;
        sW[k * 64 + o] = W1[idx];
    }
    int n0 = blockIdx.x * 4;
#pragma unroll
    for (int r = 0; r < 4; r++) {
        int n = n0 + r;
        if (n < NN)
            for (int k = tid; k < HD; k += 256) sx[r][k] = x[n * HD + k];
    }
    __syncthreads();
    int r = tid / 64, o = tid % 64;
    int n = n0 + r;
    if (n >= NN) return;
    float acc = b1[o];
#pragma unroll 8
    for (int k = 0; k < HD; k++) acc = fmaf(sx[r][k], sW[k * 64 + o], acc);
    g_h[n * 64 + o] = acc;
}

// ---------------- K2: edge coeff MLP (the big one) --------------------------
// c1 = silu(cji) @ W2^T  (9x64 -> 9x32);  c2 = silu(c1) @ W3^T (9x32 -> 9x64)
// cji_c = c2[:, :32] stored raw; ckj = c2[:,32:] stored row-L2-normalized.
__global__ void __launch_bounds__(256) k2_coeff(const float* __restrict__ cji,
                                                const float* __restrict__ W2,
                                                const float* __restrict__ W3) {
    __shared__ __align__(16) float sW2[32 * 68];      // [c][k], stride 68 (pad)
    __shared__ __align__(16) float sW3[64 * 36];      // [o][k], stride 36 (pad)
    __shared__ __align__(16) float sA[8][NORB * 64];  // silu(cji) per warp
    __shared__ __align__(16) float sC1[8][NORB * 32]; // silu(c1) per warp
    int tid = threadIdx.x;
    for (int idx = tid; idx < 32 * 64; idx += 256) {
        int c = idx / 64, k = idx % 64;
        sW2[c * 68 + k] = W2[idx];
    }
    for (int idx = tid; idx < 64 * 32; idx += 256) {
        int o = idx / 32, k = idx % 32;
        sW3[o * 36 + k] = W3[idx];
    }
    __syncthreads();

    int w = tid >> 5, lane = tid & 31;
    int e = blockIdx.x * 8 + w;
    if (e >= NE) return;

    // stage silu(cji) row block
    const float* src = cji + (size_t)e * (NORB * CFD);
    for (int i = lane; i < NORB * CFD; i += 32) sA[w][i] = silu(src[i]);
    __syncwarp();

    // GEMM1: lane = output column
    float a1[NORB];
#pragma unroll
    for (int o = 0; o < NORB; o++) a1[o] = 0.f;
#pragma unroll 4
    for (int k4 = 0; k4 < 16; k4++) {
        float4 wv = *(const float4*)&sW2[lane * 68 + k4 * 4];
#pragma unroll
        for (int o = 0; o < NORB; o++) {
            float4 av = *(const float4*)&sA[w][o * 64 + k4 * 4];
            a1[o] = fmaf(av.x, wv.x, fmaf(av.y, wv.y, fmaf(av.z, wv.z, fmaf(av.w, wv.w, a1[o]))));
        }
    }
#pragma unroll
    for (int o = 0; o < NORB; o++) sC1[w][o * 32 + lane] = silu(a1[o]);
    __syncwarp();

    // GEMM2: lane covers output columns lane and lane+32
    float aA[NORB], aB[NORB];
#pragma unroll
    for (int o = 0; o < NORB; o++) { aA[o] = 0.f; aB[o] = 0.f; }
#pragma unroll 4
    for (int k4 = 0; k4 < 8; k4++) {
        float4 wa = *(const float4*)&sW3[lane * 36 + k4 * 4];
        float4 wb = *(const float4*)&sW3[(lane + 32) * 36 + k4 * 4];
#pragma unroll
        for (int o = 0; o < NORB; o++) {
            float4 av = *(const float4*)&sC1[w][o * 32 + k4 * 4];
            aA[o] = fmaf(av.x, wa.x, fmaf(av.y, wa.y, fmaf(av.z, wa.z, fmaf(av.w, wa.w, aA[o]))));
            aB[o] = fmaf(av.x, wb.x, fmaf(av.y, wb.y, fmaf(av.z, wb.z, fmaf(av.w, wb.w, aB[o]))));
        }
    }
    size_t base = (size_t)e * (NORB * CD);
#pragma unroll
    for (int o = 0; o < NORB; o++) {
        g_cji_c[base + o * 32 + lane] = aA[o];
        float s = warp_sum(aB[o] * aB[o]);
        float inv = 1.f / fmaxf(sqrtf(s), 1e-12f);
        g_ckj_n[base + o * 32 + lane] = aB[o] * inv;
    }
}

// ---------------- K3: triplets -> edge aggregation --------------------------
__global__ void __launch_bounds__(256) k3_tri(const float* __restrict__ shb,
                                              const int* __restrict__ e_kj,
                                              const int* __restrict__ e_ji,
                                              const int* __restrict__ t_k) {
    int w = threadIdx.x >> 5, lane = threadIdx.x & 31;
    int t = blockIdx.x * 8 + w;
    if (t >= NT) return;
    int kj = e_kj[t], ji = e_ji[t], kn = t_k[t];
    float acc = 0.f;
#pragma unroll
    for (int d = 0; d < NORB; d++) {
        float cf = __ldg(&g_rbw[kj * NORB + d]) * __ldg(&shb[t * NORB + d]);
        acc = fmaf(cf, __ldg(&g_ckj_n[((size_t)kj * NORB + d) * CD + lane]), acc);
    }
    float s = warp_sum(acc * acc);
    float inv = 1.f / fmaxf(sqrtf(s), 1e-12f);
    float tw = acc * inv * sigm(g_h[kn * 64 + 32 + lane]);
    atomicAdd(&g_agg[(size_t)ji * CD + lane], tw);
}

// ---------------- K4: tbw = silu(agg) @ W4^T + b4 ----------------------------
__global__ void __launch_bounds__(256) k4_tbw(const float* __restrict__ W4,
                                              const float* __restrict__ b4) {
    __shared__ float sW[32 * 32]; // [k][c]
    __shared__ float sag[8][32];
    int tid = threadIdx.x;
    for (int idx = tid; idx < 1024; idx += 256) {
        int c = idx / 32, k = idx % 32;
        sW[k * 32 + c] = W4[idx];
    }
    __syncthreads();
    int w = tid >> 5, lane = tid & 31;
    int e = blockIdx.x * 8 + w;
    if (e >= NE) return;
    sag[w][lane] = silu(g_agg[(size_t)e * CD + lane]);
    __syncwarp();
    float acc = b4[lane];
#pragma unroll
    for (int k = 0; k < 32; k++) acc = fmaf(sag[w][k], sW[k * 32 + lane], acc);
    g_tbw[(size_t)e * CD + lane] = acc;
}

// ---------------- K5: edge finalize (lcao + node-feature MLP + scatter) ------
__global__ void __launch_bounds__(256) k5_edge(const float* __restrict__ W5,
                                               const float* __restrict__ b5,
                                               const float* __restrict__ W6,
                                               const float* __restrict__ b6,
                                               const int* __restrict__ idx_i,
                                               const int* __restrict__ idx_j) {
    __shared__ float sW5[64 * 32]; // [k][c]
    __shared__ float sW6[32 * 32]; // [k][c]
    __shared__ float su[8][64];
    __shared__ float sn[8][32];
    int tid = threadIdx.x;
    for (int idx = tid; idx < 32 * 64; idx += 256) {
        int c = idx / 64, k = idx % 64;
        sW5[k * 32 + c] = W5[idx];
    }
    for (int idx = tid; idx < 32 * 32; idx += 256) {
        int c = idx / 32, k = idx % 32;
        sW6[k * 32 + c] = W6[idx];
    }
    __syncthreads();
    int w = tid >> 5, lane = tid & 31;
    int e = blockIdx.x * 8 + w;
    if (e >= NE) return;

    float tb = 1.f + g_tbw[(size_t)e * CD + lane];
    float v[NORB];
    size_t base = (size_t)e * (NORB * CD);
#pragma unroll
    for (int d = 0; d < NORB; d++) v[d] = g_cji_c[base + d * 32 + lane] * tb;
    float lc = 0.f;
#pragma unroll
    for (int d = 0; d < NORB; d++) {
        float s = warp_sum(v[d] * v[d]);
        float inv = 1.f / fmaxf(sqrtf(s), 1e-12f);
        lc = fmaf(__ldg(&g_rbw[e * NORB + d]), v[d] * inv, lc);
    }
    float s = warp_sum(lc * lc);
    lc *= 1.f / fmaxf(sqrtf(s), 1e-12f);

    int ni = idx_i[e], nj = idx_j[e];
    su[w][lane] = silu(g_h[ni * 64 + lane]);
    su[w][lane + 32] = silu(g_h[nj * 64 + lane]);
    __syncwarp();
    float a1 = b5[lane];
#pragma unroll
    for (int k = 0; k < 64; k++) a1 = fmaf(su[w][k], sW5[k * 32 + lane], a1);
    sn[w][lane] = silu(a1);
    __syncwarp();
    float a2 = b6[lane];
#pragma unroll
    for (int k = 0; k < 32; k++) a2 = fmaf(sn[w][k], sW6[k * 32 + lane], a2);
    atomicAdd(&g_acc[ni * CD + lane], lc * a2);
}

// ---------------- K6: out = x + acc @ W7^T ----------------------------------
__global__ void __launch_bounds__(256) k6_out(const float* __restrict__ x,
                                              const float* __restrict__ W7,
                                              float* __restrict__ out) {
    __shared__ float sW[32 * 128]; // [c][hc]
    __shared__ float sa[2][32];
    int tid = threadIdx.x;
    for (int idx = tid; idx < 128 * 32; idx += 256) {
        int hc = idx / 32, c = idx % 32;
        sW[c * 128 + hc] = W7[idx];
    }
    int n0 = blockIdx.x * 2;
    if (tid < 64) {
        int r = tid >> 5, c = tid & 31;
        int n = n0 + r;
        if (n < NN) sa[r][c] = g_acc[n * 32 + c];
    }
    __syncthreads();
    int r = tid >> 7, hc = tid & 127;
    int n = n0 + r;
    if (n >= NN) return;
    float acc = x[n * 128 + hc];
#pragma unroll
    for (int c = 0; c < 32; c++) acc = fmaf(sa[r][c], sW[c * 128 + hc], acc);
    out[n * 128 + hc] = acc;
}

// ---------------- host launcher ---------------------------------------------
extern "C" void kernel_launch(void* const* d_in, const int* in_sizes, int n_in,
                              void* d_out, int out_size) {
    // Resolve input ordering: setup_inputs dict order vs reference signature order.
    int o_ii, o_ij, o_tk, o_ekj, o_eji;
    int o_W1, o_b1, o_W2, o_W3, o_W4, o_b4, o_W5, o_b5, o_W6, o_b6, o_W7;
    if (in_sizes[5] == NE) { // dict order: idx_i at slot 5
        o_ii = 5; o_ij = 6; o_tk = 7; o_ekj = 8; o_eji = 9;
        o_W1 = 10; o_b1 = 11; o_W2 = 12; o_W3 = 13; o_W4 = 14; o_b4 = 15;
        o_W5 = 16; o_b5 = 17; o_W6 = 18; o_b6 = 19; o_W7 = 20;
    } else {                 // signature order: W1 at slot 5
        o_W1 = 5; o_b1 = 6; o_W2 = 7; o_W3 = 8; o_W4 = 9; o_b4 = 10;
        o_W5 = 11; o_b5 = 12; o_W6 = 13; o_b6 = 14; o_W7 = 15;
        o_ii = 16; o_ij = 17; o_tk = 18; o_ekj = 19; o_eji = 20;
    }
    const float* x   = (const float*)d_in[0];
    const float* cji = (const float*)d_in[1];
    const float* cw  = (const float*)d_in[2];
    const float* rb  = (const float*)d_in[3];
    const float* shb = (const float*)d_in[4];
    const int* ii  = (const int*)d_in[o_ii];
    const int* ij  = (const int*)d_in[o_ij];
    const int* tk  = (const int*)d_in[o_tk];
    const int* ekj = (const int*)d_in[o_ekj];
    const int* eji = (const int*)d_in[o_eji];
    const float* W1 = (const float*)d_in[o_W1];
    const float* b1 = (const float*)d_in[o_b1];
    const float* W2 = (const float*)d_in[o_W2];
    const float* W3 = (const float*)d_in[o_W3];
    const float* W4 = (const float*)d_in[o_W4];
    const float* b4 = (const float*)d_in[o_b4];
    const float* W5 = (const float*)d_in[o_W5];
    const float* b5 = (const float*)d_in[o_b5];
    const float* W6 = (const float*)d_in[o_W6];
    const float* b6 = (const float*)d_in[o_b6];
    const float* W7 = (const float*)d_in[o_W7];
    float* out = (float*)d_out;

    k0_init<<<(NE * CD + 255) / 256, 256>>>(rb, cw);
    k1_node<<<(NN + 3) / 4, 256>>>(x, W1, b1);
    k2_coeff<<<(NE + 7) / 8, 256>>>(cji, W2, W3);
    k3_tri<<<(NT + 7) / 8, 256>>>(shb, ekj, eji, tk);
    k4_tbw<<<(NE + 7) / 8, 256>>>(W4, b4);
    k5_edge<<<(NE + 7) / 8, 256>>>(W5, b5, W6, b6, ii, ij);
    k6_out<<<(NN + 1) / 2, 256>>>(x, W7, out);
}

// round 2
// speedup vs baseline: 1.3806x; 1.3806x over previous
#include <cuda_runtime.h>
#include <math.h>

#define NN 10000
#define NE 200000
#define NT 400000
#define NORB 9
#define HD 128
#define CFD 64
#define CD 32

typedef unsigned long long u64;

// ---------------- scratch (device globals; no allocation allowed) ----------
__device__ float g_h[NN * 64];                    // node MLP out: xh=[0:32), xk=[32:64)
__device__ float g_cji_c[(size_t)NE * NORB * CD]; // 230.4 MB
__device__ float g_ckj_n[(size_t)NE * NORB * CD]; // 230.4 MB (pre-normalized ckj)
__device__ float g_rbw[NE * NORB];
__device__ float g_agg[(size_t)NE * CD];
__device__ float g_acc[NN * CD];

__device__ __forceinline__ float sigm(float x) { return 1.f / (1.f + __expf(-x)); }
__device__ __forceinline__ float silu(float x) { return x * sigm(x); }

__device__ __forceinline__ float warp_sum(float s) {
#pragma unroll
    for (int off = 16; off; off >>= 1) s += __shfl_xor_sync(0xffffffffu, s, off);
    return s;
}

// ---- packed fp32x2 helpers (Blackwell FFMA2 — PTX-only, 2x FFMA density) ----
__device__ __forceinline__ u64 pk(float x, float y) {
    u64 r; asm("mov.b64 %0,{%1,%2};" : "=l"(r) : "f"(x), "f"(y)); return r;
}
__device__ __forceinline__ void fma2(u64& d, u64 a, u64 b) {
    asm("fma.rn.f32x2 %0,%1,%2,%0;" : "+l"(d) : "l"(a), "l"(b));
}
__device__ __forceinline__ float unp_sum(u64 v) {
    float x, y; asm("mov.b64 {%0,%1},%2;" : "=f"(x), "=f"(y) : "l"(v)); return x + y;
}

// ---------------- K0: zero accumulators + rb_w = rb * cutoff_w -------------
__global__ void k0_init(const float* __restrict__ rb, const float* __restrict__ cw) {
    int i = blockIdx.x * blockDim.x + threadIdx.x;
    if (i < NE * CD) g_agg[i] = 0.f;
    if (i < NN * CD) g_acc[i] = 0.f;
    if (i < NE * NORB) g_rbw[i] = rb[i] * cw[i / NORB];
}

// ---------------- K1: h = x @ W1^T + b1 ------------------------------------
__global__ void __launch_bounds__(256) k1_node(const float* __restrict__ x,
                                               const float* __restrict__ W1,
                                               const float* __restrict__ b1) {
    __shared__ float sW[HD * 64];   // transposed [k][o]
    __shared__ float sx[4][HD];
    int tid = threadIdx.x;
    for (int idx = tid; idx < 64 * HD; idx += 256) {
        int o = idx / HD, k = idx % HD;
        sW[k * 64 + o] = W1[idx];
    }
    int n0 = blockIdx.x * 4;
#pragma unroll
    for (int r = 0; r < 4; r++) {
        int n = n0 + r;
        if (n < NN)
            for (int k = tid; k < HD; k += 256) sx[r][k] = x[n * HD + k];
    }
    __syncthreads();
    int r = tid / 64, o = tid % 64;
    int n = n0 + r;
    if (n >= NN) return;
    float acc = b1[o];
#pragma unroll 8
    for (int k = 0; k < HD; k++) acc = fmaf(sx[r][k], sW[k * 64 + o], acc);
    g_h[n * 64 + o] = acc;
}

// ---------------- K2: edge coeff MLP (the big one, FFMA2) --------------------
// c1 = silu(cji) @ W2^T  (9x64 -> 9x32);  c2 = silu(c1) @ W3^T (9x32 -> 9x64)
// cji_c = c2[:, :32] stored raw; ckj = c2[:,32:] stored row-L2-normalized.
__global__ void __launch_bounds__(256) k2_coeff(const float* __restrict__ cji,
                                                const float* __restrict__ W2,
                                                const float* __restrict__ W3) {
    __shared__ __align__(16) float sW2[32 * 68];      // [c][k], stride 68 (pad)
    __shared__ __align__(16) float sW3[64 * 36];      // [o][k], stride 36 (pad)
    __shared__ __align__(16) float sA[8][NORB * 64];  // silu(cji) per warp
    __shared__ __align__(16) float sC1[8][NORB * 32]; // silu(c1) per warp
    int tid = threadIdx.x;
    for (int idx = tid; idx < 32 * 64; idx += 256) {
        int c = idx / 64, k = idx % 64;
        sW2[c * 68 + k] = W2[idx];
    }
    for (int idx = tid; idx < 64 * 32; idx += 256) {
        int o = idx / 32, k = idx % 32;
        sW3[o * 36 + k] = W3[idx];
    }
    __syncthreads();

    int w = tid >> 5, lane = tid & 31;
    int e = blockIdx.x * 8 + w;
    if (e >= NE) return;

    // stage silu(cji) row block (vectorized, coalesced)
    const float4* src4 = (const float4*)(cji + (size_t)e * (NORB * CFD));
    float4* dst4 = (float4*)sA[w];
    for (int i = lane; i < NORB * CFD / 4; i += 32) {
        float4 v = src4[i];
        v.x = silu(v.x); v.y = silu(v.y); v.z = silu(v.z); v.w = silu(v.w);
        dst4[i] = v;
    }
    __syncwarp();

    // GEMM1: lane = output column, packed over k
    u64 acc1[NORB];
#pragma unroll
    for (int o = 0; o < NORB; o++) acc1[o] = 0ull;
#pragma unroll
    for (int k4 = 0; k4 < 16; k4++) {
        float4 wv = *(const float4*)&sW2[lane * 68 + k4 * 4];
        u64 w0 = pk(wv.x, wv.y), w1 = pk(wv.z, wv.w);
#pragma unroll
        for (int o = 0; o < NORB; o++) {
            float4 av = *(const float4*)&sA[w][o * 64 + k4 * 4];
            fma2(acc1[o], pk(av.x, av.y), w0);
            fma2(acc1[o], pk(av.z, av.w), w1);
        }
    }
#pragma unroll
    for (int o = 0; o < NORB; o++) sC1[w][o * 32 + lane] = silu(unp_sum(acc1[o]));
    __syncwarp();

    // GEMM2: lane covers output columns lane and lane+32, packed over k
    u64 aA[NORB], aB[NORB];
#pragma unroll
    for (int o = 0; o < NORB; o++) { aA[o] = 0ull; aB[o] = 0ull; }
#pragma unroll
    for (int k4 = 0; k4 < 8; k4++) {
        float4 wa = *(const float4*)&sW3[lane * 36 + k4 * 4];
        float4 wb = *(const float4*)&sW3[(lane + 32) * 36 + k4 * 4];
        u64 wa0 = pk(wa.x, wa.y), wa1 = pk(wa.z, wa.w);
        u64 wb0 = pk(wb.x, wb.y), wb1 = pk(wb.z, wb.w);
#pragma unroll
        for (int o = 0; o < NORB; o++) {
            float4 av = *(const float4*)&sC1[w][o * 32 + k4 * 4];
            u64 a0 = pk(av.x, av.y), a1 = pk(av.z, av.w);
            fma2(aA[o], a0, wa0); fma2(aA[o], a1, wa1);
            fma2(aB[o], a0, wb0); fma2(aB[o], a1, wb1);
        }
    }
    size_t base = (size_t)e * (NORB * CD);
#pragma unroll
    for (int o = 0; o < NORB; o++) {
        float va = unp_sum(aA[o]);
        float vb = unp_sum(aB[o]);
        g_cji_c[base + o * 32 + lane] = va;
        float s = warp_sum(vb * vb);
        float inv = 1.f / fmaxf(sqrtf(s), 1e-12f);
        g_ckj_n[base + o * 32 + lane] = vb * inv;
    }
}

// ---------------- K3: triplets -> edge aggregation --------------------------
__global__ void __launch_bounds__(256) k3_tri(const float* __restrict__ shb,
                                              const int* __restrict__ e_kj,
                                              const int* __restrict__ e_ji,
                                              const int* __restrict__ t_k) {
    int w = threadIdx.x >> 5, lane = threadIdx.x & 31;
    int t = blockIdx.x * 8 + w;
    if (t >= NT) return;
    int kj = e_kj[t], ji = e_ji[t], kn = t_k[t];
    float acc = 0.f;
#pragma unroll
    for (int d = 0; d < NORB; d++) {
        float cf = __ldg(&g_rbw[kj * NORB + d]) * __ldg(&shb[t * NORB + d]);
        acc = fmaf(cf, __ldg(&g_ckj_n[((size_t)kj * NORB + d) * CD + lane]), acc);
    }
    float s = warp_sum(acc * acc);
    float inv = 1.f / fmaxf(sqrtf(s), 1e-12f);
    float tw = acc * inv * sigm(g_h[kn * 64 + 32 + lane]);
    atomicAdd(&g_agg[(size_t)ji * CD + lane], tw);
}

// ---------------- K5: edge finalize (fused tbw + lcao + node MLP + scatter) --
__global__ void __launch_bounds__(256) k5_edge(const float* __restrict__ W4,
                                               const float* __restrict__ b4,
                                               const float* __restrict__ W5,
                                               const float* __restrict__ b5,
                                               const float* __restrict__ W6,
                                               const float* __restrict__ b6,
                                               const int* __restrict__ idx_i,
                                               const int* __restrict__ idx_j) {
    __shared__ __align__(16) float sW4[32 * 36]; // [c][k] pad 36
    __shared__ __align__(16) float sW5[32 * 68]; // [c][k] pad 68
    __shared__ __align__(16) float sW6[32 * 36]; // [c][k] pad 36
    __shared__ __align__(16) float sag[8][32];
    __shared__ __align__(16) float su[8][64];
    __shared__ __align__(16) float sn[8][32];
    int tid = threadIdx.x;
    for (int idx = tid; idx < 32 * 32; idx += 256) {
        int c = idx / 32, k = idx % 32;
        sW4[c * 36 + k] = W4[idx];
        sW6[c * 36 + k] = W6[idx];
    }
    for (int idx = tid; idx < 32 * 64; idx += 256) {
        int c = idx / 64, k = idx % 64;
        sW5[c * 68 + k] = W5[idx];
    }
    __syncthreads();
    int w = tid >> 5, lane = tid & 31;
    int e = blockIdx.x * 8 + w;
    if (e >= NE) return;

    // tbw = silu(agg) @ W4^T + b4   (fused former k4)
    sag[w][lane] = silu(g_agg[(size_t)e * CD + lane]);
    __syncwarp();
    u64 t2 = 0ull;
#pragma unroll
    for (int k4 = 0; k4 < 8; k4++) {
        float4 wv = *(const float4*)&sW4[lane * 36 + k4 * 4];
        float4 av = *(const float4*)&sag[w][k4 * 4];
        fma2(t2, pk(av.x, av.y), pk(wv.x, wv.y));
        fma2(t2, pk(av.z, av.w), pk(wv.z, wv.w));
    }
    float tb = 1.f + b4[lane] + unp_sum(t2);

    // lcao_w = l2norm( sum_d rbw[d] * l2norm(cji_c[d,:]*tb) )
    float v[NORB];
    size_t base = (size_t)e * (NORB * CD);
#pragma unroll
    for (int d = 0; d < NORB; d++) v[d] = g_cji_c[base + d * 32 + lane] * tb;
    float lc = 0.f;
#pragma unroll
    for (int d = 0; d < NORB; d++) {
        float s = warp_sum(v[d] * v[d]);
        float inv = 1.f / fmaxf(sqrtf(s), 1e-12f);
        lc = fmaf(__ldg(&g_rbw[e * NORB + d]), v[d] * inv, lc);
    }
    float s = warp_sum(lc * lc);
    lc *= 1.f / fmaxf(sqrtf(s), 1e-12f);

    // node-feature MLP
    int ni = idx_i[e], nj = idx_j[e];
    su[w][lane] = silu(g_h[ni * 64 + lane]);
    su[w][lane + 32] = silu(g_h[nj * 64 + lane]);
    __syncwarp();
    u64 a2 = 0ull;
#pragma unroll
    for (int k4 = 0; k4 < 16; k4++) {
        float4 wv = *(const float4*)&sW5[lane * 68 + k4 * 4];
        float4 av = *(const float4*)&su[w][k4 * 4];
        fma2(a2, pk(av.x, av.y), pk(wv.x, wv.y));
        fma2(a2, pk(av.z, av.w), pk(wv.z, wv.w));
    }
    sn[w][lane] = silu(b5[lane] + unp_sum(a2));
    __syncwarp();
    u64 a3 = 0ull;
#pragma unroll
    for (int k4 = 0; k4 < 8; k4++) {
        float4 wv = *(const float4*)&sW6[lane * 36 + k4 * 4];
        float4 av = *(const float4*)&sn[w][k4 * 4];
        fma2(a3, pk(av.x, av.y), pk(wv.x, wv.y));
        fma2(a3, pk(av.z, av.w), pk(wv.z, wv.w));
    }
    float nf = b6[lane] + unp_sum(a3);
    atomicAdd(&g_acc[ni * CD + lane], lc * nf);
}

// ---------------- K6: out = x + acc @ W7^T ----------------------------------
__global__ void __launch_bounds__(256) k6_out(const float* __restrict__ x,
                                              const float* __restrict__ W7,
                                              float* __restrict__ out) {
    __shared__ float sW[32 * 128]; // [c][hc]
    __shared__ float sa[2][32];
    int tid = threadIdx.x;
    for (int idx = tid; idx < 128 * 32; idx += 256) {
        int hc = idx / 32, c = idx % 32;
        sW[c * 128 + hc] = W7[idx];
    }
    int n0 = blockIdx.x * 2;
    if (tid < 64) {
        int r = tid >> 5, c = tid & 31;
        int n = n0 + r;
        if (n < NN) sa[r][c] = g_acc[n * 32 + c];
    }
    __syncthreads();
    int r = tid >> 7, hc = tid & 127;
    int n = n0 + r;
    if (n >= NN) return;
    float acc = x[n * 128 + hc];
#pragma unroll
    for (int c = 0; c < 32; c++) acc = fmaf(sa[r][c], sW[c * 128 + hc], acc);
    out[n * 128 + hc] = acc;
}

// ---------------- host launcher ---------------------------------------------
extern "C" void kernel_launch(void* const* d_in, const int* in_sizes, int n_in,
                              void* d_out, int out_size) {
    int o_ii, o_ij, o_tk, o_ekj, o_eji;
    int o_W1, o_b1, o_W2, o_W3, o_W4, o_b4, o_W5, o_b5, o_W6, o_b6, o_W7;
    if (in_sizes[5] == NE) { // dict order: idx_i at slot 5
        o_ii = 5; o_ij = 6; o_tk = 7; o_ekj = 8; o_eji = 9;
        o_W1 = 10; o_b1 = 11; o_W2 = 12; o_W3 = 13; o_W4 = 14; o_b4 = 15;
        o_W5 = 16; o_b5 = 17; o_W6 = 18; o_b6 = 19; o_W7 = 20;
    } else {                 // signature order: W1 at slot 5
        o_W1 = 5; o_b1 = 6; o_W2 = 7; o_W3 = 8; o_W4 = 9; o_b4 = 10;
        o_W5 = 11; o_b5 = 12; o_W6 = 13; o_b6 = 14; o_b6 = 14; o_W7 = 15;
        o_W6 = 13; o_b6 = 14;
        o_ii = 16; o_ij = 17; o_tk = 18; o_ekj = 19; o_eji = 20;
    }
    const float* x   = (const float*)d_in[0];
    const float* cji = (const float*)d_in[1];
    const float* cw  = (const float*)d_in[2];
    const float* rb  = (const float*)d_in[3];
    const float* shb = (const float*)d_in[4];
    const int* ii  = (const int*)d_in[o_ii];
    const int* ij  = (const int*)d_in[o_ij];
    const int* tk  = (const int*)d_in[o_tk];
    const int* ekj = (const int*)d_in[o_ekj];
    const int* eji = (const int*)d_in[o_eji];
    const float* W1 = (const float*)d_in[o_W1];
    const float* b1 = (const float*)d_in[o_b1];
    const float* W2 = (const float*)d_in[o_W2];
    const float* W3 = (const float*)d_in[o_W3];
    const float* W4 = (const float*)d_in[o_W4];
    const float* b4 = (const float*)d_in[o_b4];
    const float* W5 = (const float*)d_in[o_W5];
    const float* b5 = (const float*)d_in[o_b5];
    const float* W6 = (const float*)d_in[o_W6];
    const float* b6 = (const float*)d_in[o_b6];
    const float* W7 = (const float*)d_in[o_W7];
    float* out = (float*)d_out;

    k0_init<<<(NE * CD + 255) / 256, 256>>>(rb, cw);
    k1_node<<<(NN + 3) / 4, 256>>>(x, W1, b1);
    k2_coeff<<<(NE + 7) / 8, 256>>>(cji, W2, W3);
    k3_tri<<<(NT + 7) / 8, 256>>>(shb, ekj, eji, tk);
    k5_edge<<<(NE + 7) / 8, 256>>>(W4, b4, W5, b5, W6, b6, ii, ij);
    k6_out<<<(NN + 1) / 2, 256>>>(x, W7, out);
}

// round 4
// speedup vs baseline: 1.4488x; 1.0494x over previous
#include <cuda_runtime.h>
#include <math.h>

#define NN 10000
#define NE 200000
#define NT 400000
#define NORB 9
#define HD 128
#define CFD 64
#define CD 32

typedef unsigned long long u64;

// ---------------- scratch (device globals; no allocation allowed) ----------
__device__ float g_h[NN * 64];                    // node MLP out: xh=[0:32), xk=[32:64)
__device__ float g_cji_c[(size_t)NE * NORB * CD]; // 230.4 MB
__device__ float g_ckj_n[(size_t)NE * NORB * CD]; // 230.4 MB (pre-normalized ckj)
__device__ float g_rbw[NE * NORB];
__device__ float g_agg[(size_t)NE * CD];
__device__ float g_acc[NN * CD];

__device__ __forceinline__ float sigm(float x) { return 1.f / (1.f + __expf(-x)); }
__device__ __forceinline__ float silu(float x) { return x * sigm(x); }

__device__ __forceinline__ float warp_sum(float s) {
#pragma unroll
    for (int off = 16; off; off >>= 1) s += __shfl_xor_sync(0xffffffffu, s, off);
    return s;
}

// ---- packed fp32x2 FFMA2: operands must already live in u64 register pairs --
__device__ __forceinline__ void fma2(u64& d, u64 a, u64 b) {
    asm("fma.rn.f32x2 %0,%1,%2,%0;" : "+l"(d) : "l"(a), "l"(b));
}
__device__ __forceinline__ float unp_sum(u64 v) {
    float x, y; asm("mov.b64 {%0,%1},%2;" : "=f"(x), "=f"(y) : "l"(v)); return x + y;
}

// ---------------- K0: zero accumulators + rb_w = rb * cutoff_w -------------
__global__ void k0_init(const float* __restrict__ rb, const float* __restrict__ cw) {
    int i = blockIdx.x * blockDim.x + threadIdx.x;
    if (i < NE * CD) g_agg[i] = 0.f;
    if (i < NN * CD) g_acc[i] = 0.f;
    if (i < NE * NORB) g_rbw[i] = rb[i] * cw[i / NORB];
}

// ---------------- K1: h = x @ W1^T + b1 ------------------------------------
__global__ void __launch_bounds__(256) k1_node(const float* __restrict__ x,
                                               const float* __restrict__ W1,
                                               const float* __restrict__ b1) {
    __shared__ float sW[HD * 64];   // transposed [k][o]
    __shared__ float sx[4][HD];
    int tid = threadIdx.x;
    for (int idx = tid; idx < 64 * HD; idx += 256) {
        int o = idx / HD, k = idx % HD;
        sW[k * 64 + o] = W1[idx];
    }
    int n0 = blockIdx.x * 4;
#pragma unroll
    for (int r = 0; r < 4; r++) {
        int n = n0 + r;
        if (n < NN)
            for (int k = tid; k < HD; k += 256) sx[r][k] = x[n * HD + k];
    }
    __syncthreads();
    int r = tid / 64, o = tid % 64;
    int n = n0 + r;
    if (n >= NN) return;
    float acc = b1[o];
#pragma unroll 8
    for (int k = 0; k < HD; k++) acc = fmaf(sx[r][k], sW[k * 64 + o], acc);
    g_h[n * 64 + o] = acc;
}

// ---------------- K2: edge coeff MLP (FFMA2, zero-packing inner loops) -------
// c1 = silu(cji) @ W2^T  (9x64 -> 9x32);  c2 = silu(c1) @ W3^T (9x32 -> 9x64)
// cji_c = c2[:, :32] stored raw; ckj = c2[:,32:] stored row-L2-normalized.
__global__ void __launch_bounds__(256) k2_coeff(const float* __restrict__ cji,
                                                const float* __restrict__ W2,
                                                const float* __restrict__ W3) {
    __shared__ __align__(16) float sW2[32 * 68];      // [c][k], stride 68 (pad)
    __shared__ __align__(16) float sW3[64 * 36];      // [o][k], stride 36 (pad)
    __shared__ __align__(16) float sA[8][NORB * 64];  // silu(cji) per warp
    __shared__ __align__(16) float sC1[8][NORB * 32]; // silu(c1) per warp
    int tid = threadIdx.x;
    for (int idx = tid; idx < 32 * 64; idx += 256) {
        int c = idx / 64, k = idx % 64;
        sW2[c * 68 + k] = W2[idx];
    }
    for (int idx = tid; idx < 64 * 32; idx += 256) {
        int o = idx / 32, k = idx % 32;
        sW3[o * 36 + k] = W3[idx];
    }
    __syncthreads();

    int w = tid >> 5, lane = tid & 31;
    int e = blockIdx.x * 8 + w;
    if (e >= NE) return;

    // stage silu(cji) row block (vectorized, coalesced)
    const float4* src4 = (const float4*)(cji + (size_t)e * (NORB * CFD));
    float4* dst4 = (float4*)sA[w];
    for (int i = lane; i < NORB * CFD / 4; i += 32) {
        float4 v = src4[i];
        v.x = silu(v.x); v.y = silu(v.y); v.z = silu(v.z); v.w = silu(v.w);
        dst4[i] = v;
    }
    __syncwarp();

    // GEMM1: lane = output column; LDS.128 -> two FFMA2, no packing movs
    u64 acc1[NORB];
#pragma unroll
    for (int o = 0; o < NORB; o++) acc1[o] = 0ull;
#pragma unroll
    for (int k4 = 0; k4 < 16; k4++) {
        ulonglong2 wv = *(const ulonglong2*)&sW2[lane * 68 + k4 * 4];
#pragma unroll
        for (int o = 0; o < NORB; o++) {
            ulonglong2 av = *(const ulonglong2*)&sA[w][o * 64 + k4 * 4];
            fma2(acc1[o], av.x, wv.x);
            fma2(acc1[o], av.y, wv.y);
        }
    }
#pragma unroll
    for (int o = 0; o < NORB; o++) sC1[w][o * 32 + lane] = silu(unp_sum(acc1[o]));
    __syncwarp();

    // GEMM2: lane covers output columns lane and lane+32
    u64 aA[NORB], aB[NORB];
#pragma unroll
    for (int o = 0; o < NORB; o++) { aA[o] = 0ull; aB[o] = 0ull; }
#pragma unroll
    for (int k4 = 0; k4 < 8; k4++) {
        ulonglong2 wa = *(const ulonglong2*)&sW3[lane * 36 + k4 * 4];
        ulonglong2 wb = *(const ulonglong2*)&sW3[(lane + 32) * 36 + k4 * 4];
#pragma unroll
        for (int o = 0; o < NORB; o++) {
            ulonglong2 av = *(const ulonglong2*)&sC1[w][o * 32 + k4 * 4];
            fma2(aA[o], av.x, wa.x); fma2(aA[o], av.y, wa.y);
            fma2(aB[o], av.x, wb.x); fma2(aB[o], av.y, wb.y);
        }
    }
    size_t base = (size_t)e * (NORB * CD);
#pragma unroll
    for (int o = 0; o < NORB; o++) {
        float va = unp_sum(aA[o]);
        float vb = unp_sum(aB[o]);
        g_cji_c[base + o * 32 + lane] = va;
        float s = warp_sum(vb * vb);
        float inv = 1.f / fmaxf(sqrtf(s), 1e-12f);
        g_ckj_n[base + o * 32 + lane] = vb * inv;
    }
}

// ---------------- K3: triplets -> edge aggregation --------------------------
__global__ void __launch_bounds__(256) k3_tri(const float* __restrict__ shb,
                                              const int* __restrict__ e_kj,
                                              const int* __restrict__ e_ji,
                                              const int* __restrict__ t_k) {
    int w = threadIdx.x >> 5, lane = threadIdx.x & 31;
    int t = blockIdx.x * 8 + w;
    if (t >= NT) return;
    int kj = e_kj[t], ji = e_ji[t], kn = t_k[t];
    float acc = 0.f;
#pragma unroll
    for (int d = 0; d < NORB; d++) {
        float cf = __ldg(&g_rbw[kj * NORB + d]) * __ldg(&shb[t * NORB + d]);
        acc = fmaf(cf, __ldg(&g_ckj_n[((size_t)kj * NORB + d) * CD + lane]), acc);
    }
    float s = warp_sum(acc * acc);
    float inv = 1.f / fmaxf(sqrtf(s), 1e-12f);
    float tw = acc * inv * sigm(g_h[kn * 64 + 32 + lane]);
    atomicAdd(&g_agg[(size_t)ji * CD + lane], tw);
}

// ---------------- K5: edge finalize (fused tbw + lcao + node MLP + scatter) --
__global__ void __launch_bounds__(256) k5_edge(const float* __restrict__ W4,
                                               const float* __restrict__ b4,
                                               const float* __restrict__ W5,
                                               const float* __restrict__ b5,
                                               const float* __restrict__ W6,
                                               const float* __restrict__ b6,
                                               const int* __restrict__ idx_i,
                                               const int* __restrict__ idx_j) {
    __shared__ __align__(16) float sW4[32 * 36]; // [c][k] pad 36
    __shared__ __align__(16) float sW5[32 * 68]; // [c][k] pad 68
    __shared__ __align__(16) float sW6[32 * 36]; // [c][k] pad 36
    __shared__ __align__(16) float sag[8][32];
    __shared__ __align__(16) float su[8][64];
    __shared__ __align__(16) float sn[8][32];
    int tid = threadIdx.x;
    for (int idx = tid; idx < 32 * 32; idx += 256) {
        int c = idx / 32, k = idx % 32;
        sW4[c * 36 + k] = W4[idx];
        sW6[c * 36 + k] = W6[idx];
    }
    for (int idx = tid; idx < 32 * 64; idx += 256) {
        int c = idx / 64, k = idx % 64;
        sW5[c * 68 + k] = W5[idx];
    }
    __syncthreads();
    int w = tid >> 5, lane = tid & 31;
    int e = blockIdx.x * 8 + w;
    if (e >= NE) return;

    // tbw = silu(agg) @ W4^T + b4   (fused former k4)
    sag[w][lane] = silu(g_agg[(size_t)e * CD + lane]);
    __syncwarp();
    u64 t2 = 0ull;
#pragma unroll
    for (int k4 = 0; k4 < 8; k4++) {
        ulonglong2 wv = *(const ulonglong2*)&sW4[lane * 36 + k4 * 4];
        ulonglong2 av = *(const ulonglong2*)&sag[w][k4 * 4];
        fma2(t2, av.x, wv.x);
        fma2(t2, av.y, wv.y);
    }
    float tb = 1.f + b4[lane] + unp_sum(t2);

    // lcao_w = l2norm( sum_d rbw[d] * l2norm(cji_c[d,:]*tb) )
    float v[NORB];
    size_t base = (size_t)e * (NORB * CD);
#pragma unroll
    for (int d = 0; d < NORB; d++) v[d] = g_cji_c[base + d * 32 + lane] * tb;
    float lc = 0.f;
#pragma unroll
    for (int d = 0; d < NORB; d++) {
        float s = warp_sum(v[d] * v[d]);
        float inv = 1.f / fmaxf(sqrtf(s), 1e-12f);
        lc = fmaf(__ldg(&g_rbw[e * NORB + d]), v[d] * inv, lc);
    }
    float s = warp_sum(lc * lc);
    lc *= 1.f / fmaxf(sqrtf(s), 1e-12f);

    // node-feature MLP
    int ni = idx_i[e], nj = idx_j[e];
    su[w][lane] = silu(g_h[ni * 64 + lane]);
    su[w][lane + 32] = silu(g_h[nj * 64 + lane]);
    __syncwarp();
    u64 a2 = 0ull;
#pragma unroll
    for (int k4 = 0; k4 < 16; k4++) {
        ulonglong2 wv = *(const ulonglong2*)&sW5[lane * 68 + k4 * 4];
        ulonglong2 av = *(const ulonglong2*)&su[w][k4 * 4];
        fma2(a2, av.x, wv.x);
        fma2(a2, av.y, wv.y);
    }
    sn[w][lane] = silu(b5[lane] + unp_sum(a2));
    __syncwarp();
    u64 a3 = 0ull;
#pragma unroll
    for (int k4 = 0; k4 < 8; k4++) {
        ulonglong2 wv = *(const ulonglong2*)&sW6[lane * 36 + k4 * 4];
        ulonglong2 av = *(const ulonglong2*)&sn[w][k4 * 4];
        fma2(a3, av.x, wv.x);
        fma2(a3, av.y, wv.y);
    }
    float nf = b6[lane] + unp_sum(a3);
    atomicAdd(&g_acc[ni * CD + lane], lc * nf);
}

// ---------------- K6: out = x + acc @ W7^T ----------------------------------
__global__ void __launch_bounds__(256) k6_out(const float* __restrict__ x,
                                              const float* __restrict__ W7,
                                              float* __restrict__ out) {
    __shared__ float sW[32 * 128]; // [c][hc]
    __shared__ float sa[2][32];
    int tid = threadIdx.x;
    for (int idx = tid; idx < 128 * 32; idx += 256) {
        int hc = idx / 32, c = idx % 32;
        sW[c * 128 + hc] = W7[idx];
    }
    int n0 = blockIdx.x * 2;
    if (tid < 64) {
        int r = tid >> 5, c = tid & 31;
        int n = n0 + r;
        if (n < NN) sa[r][c] = g_acc[n * 32 + c];
    }
    __syncthreads();
    int r = tid >> 7, hc = tid & 127;
    int n = n0 + r;
    if (n >= NN) return;
    float acc = x[n * 128 + hc];
#pragma unroll
    for (int c = 0; c < 32; c++) acc = fmaf(sa[r][c], sW[c * 128 + hc], acc);
    out[n * 128 + hc] = acc;
}

// ---------------- host launcher ---------------------------------------------
extern "C" void kernel_launch(void* const* d_in, const int* in_sizes, int n_in,
                              void* d_out, int out_size) {
    int o_ii, o_ij, o_tk, o_ekj, o_eji;
    int o_W1, o_b1, o_W2, o_W3, o_W4, o_b4, o_W5, o_b5, o_W6, o_b6, o_W7;
    if (in_sizes[5] == NE) { // dict order: idx_i at slot 5
        o_ii = 5; o_ij = 6; o_tk = 7; o_ekj = 8; o_eji = 9;
        o_W1 = 10; o_b1 = 11; o_W2 = 12; o_W3 = 13; o_W4 = 14; o_b4 = 15;
        o_W5 = 16; o_b5 = 17; o_W6 = 18; o_b6 = 19; o_W7 = 20;
    } else {                 // signature order: W1 at slot 5
        o_W1 = 5; o_b1 = 6; o_W2 = 7; o_W3 = 8; o_W4 = 9; o_b4 = 10;
        o_W5 = 11; o_b5 = 12; o_W6 = 13; o_b6 = 14; o_W7 = 15;
        o_ii = 16; o_ij = 17; o_tk = 18; o_ekj = 19; o_eji = 20;
    }
    const float* x   = (const float*)d_in[0];
    const float* cji = (const float*)d_in[1];
    const float* cw  = (const float*)d_in[2];
    const float* rb  = (const float*)d_in[3];
    const float* shb = (const float*)d_in[4];
    const int* ii  = (const int*)d_in[o_ii];
    const int* ij  = (const int*)d_in[o_ij];
    const int* tk  = (const int*)d_in[o_tk];
    const int* ekj = (const int*)d_in[o_ekj];
    const int* eji = (const int*)d_in[o_eji];
    const float* W1 = (const float*)d_in[o_W1];
    const float* b1 = (const float*)d_in[o_b1];
    const float* W2 = (const float*)d_in[o_W2];
    const float* W3 = (const float*)d_in[o_W3];
    const float* W4 = (const float*)d_in[o_W4];
    const float* b4 = (const float*)d_in[o_b4];
    const float* W5 = (const float*)d_in[o_W5];
    const float* b5 = (const float*)d_in[o_b5];
    const float* W6 = (const float*)d_in[o_W6];
    const float* b6 = (const float*)d_in[o_b6];
    const float* W7 = (const float*)d_in[o_W7];
    float* out = (float*)d_out;

    k0_init<<<(NE * CD + 255) / 256, 256>>>(rb, cw);
    k1_node<<<(NN + 3) / 4, 256>>>(x, W1, b1);
    k2_coeff<<<(NE + 7) / 8, 256>>>(cji, W2, W3);
    k3_tri<<<(NT + 7) / 8, 256>>>(shb, ekj, eji, tk);
    k5_edge<<<(NE + 7) / 8, 256>>>(W4, b4, W5, b5, W6, b6, ii, ij);
    k6_out<<<(NN + 1) / 2, 256>>>(x, W7, out);
}

// round 5
// speedup vs baseline: 1.8626x; 1.2857x over previous
#include <cuda_runtime.h>
#include <math.h>

#define NN 10000
#define NE 200000
#define NT 400000
#define NORB 9
#define HD 128
#define CFD 64
#define CD 32
#define R_TOT (NE * NORB)   // 1,800,000 flattened (edge,orb) rows

typedef unsigned long long u64;
typedef unsigned int u32;

// ---------------- scratch (device globals; no allocation allowed) ----------
__device__ float g_h[NN * 64];                    // node MLP out: xh=[0:32), xk=[32:64)
__device__ float g_cji_c[(size_t)NE * NORB * CD]; // 230.4 MB
__device__ float g_ckj_n[(size_t)NE * NORB * CD]; // 230.4 MB (pre-normalized ckj)
__device__ float g_rbw[NE * NORB];
__device__ float g_agg[(size_t)NE * CD];
__device__ float g_acc[NN * CD];

__device__ __forceinline__ float sigm(float x) { return 1.f / (1.f + __expf(-x)); }
__device__ __forceinline__ float silu(float x) { return x * sigm(x); }

__device__ __forceinline__ float warp_sum(float s) {
#pragma unroll
    for (int off = 16; off; off >>= 1) s += __shfl_xor_sync(0xffffffffu, s, off);
    return s;
}

// ---- packed fp32x2 FFMA2 (still used in k5) --------------------------------
__device__ __forceinline__ void fma2(u64& d, u64 a, u64 b) {
    asm("fma.rn.f32x2 %0,%1,%2,%0;" : "+l"(d) : "l"(a), "l"(b));
}
__device__ __forceinline__ float unp_sum(u64 v) {
    float x, y; asm("mov.b64 {%0,%1},%2;" : "=f"(x), "=f"(y) : "l"(v)); return x + y;
}

// ---- tf32 helpers -----------------------------------------------------------
__device__ __forceinline__ u32 to_tf32(float f) {
    u32 r; asm("cvt.rna.tf32.f32 %0,%1;" : "=r"(r) : "f"(f)); return r;
}
__device__ __forceinline__ void mma_tf32(float& c0, float& c1, float& c2, float& c3,
                                         u32 a0, u32 a1, u32 a2, u32 a3,
                                         u32 b0, u32 b1) {
    asm("mma.sync.aligned.m16n8k8.row.col.f32.tf32.tf32.f32 "
        "{%0,%1,%2,%3},{%4,%5,%6,%7},{%8,%9},{%0,%1,%2,%3};"
        : "+f"(c0), "+f"(c1), "+f"(c2), "+f"(c3)
        : "r"(a0), "r"(a1), "r"(a2), "r"(a3), "r"(b0), "r"(b1));
}

// ---------------- K0: zero accumulators + rb_w = rb * cutoff_w -------------
__global__ void k0_init(const float* __restrict__ rb, const float* __restrict__ cw) {
    int i = blockIdx.x * blockDim.x + threadIdx.x;
    if (i < NE * CD) g_agg[i] = 0.f;
    if (i < NN * CD) g_acc[i] = 0.f;
    if (i < NE * NORB) g_rbw[i] = rb[i] * cw[i / NORB];
}

// ---------------- K1: h = x @ W1^T + b1 ------------------------------------
__global__ void __launch_bounds__(256) k1_node(const float* __restrict__ x,
                                               const float* __restrict__ W1,
                                               const float* __restrict__ b1) {
    __shared__ float sW[HD * 64];
    __shared__ float sx[4][HD];
    int tid = threadIdx.x;
    for (int idx = tid; idx < 64 * HD; idx += 256) {
        int o = idx / HD, k = idx % HD;
        sW[k * 64 + o] = W1[idx];
    }
    int n0 = blockIdx.x * 4;
#pragma unroll
    for (int r = 0; r < 4; r++) {
        int n = n0 + r;
        if (n < NN)
            for (int k = tid; k < HD; k += 256) sx[r][k] = x[n * HD + k];
    }
    __syncthreads();
    int r = tid / 64, o = tid % 64;
    int n = n0 + r;
    if (n >= NN) return;
    float acc = b1[o];
#pragma unroll 8
    for (int k = 0; k < HD; k++) acc = fmaf(sx[r][k], sW[k * 64 + o], acc);
    g_h[n * 64 + o] = acc;
}

// ---------------- K2: edge coeff MLP on TENSOR CORES (tf32 mma.sync) ---------
// rows = flattened (edge,orb).  GEMM1: (R x 64)@(64x32), silu, GEMM2: (R x 32)@(32x64).
// cols [0:32) -> g_cji_c raw;  cols [32:64) -> row-l2norm -> g_ckj_n.
// Block = 256 thr (8 warps); warp owns 16 rows end-to-end; no block barrier
// after weight staging.
__global__ void __launch_bounds__(256) k2_mma(const float* __restrict__ cji,
                                              const float* __restrict__ W2,
                                              const float* __restrict__ W3) {
    __shared__ u32 sW2[32 * 68];       // [n][k] pad 68 (tf32 bits)
    __shared__ u32 sW3[64 * 36];       // [n][k] pad 36
    __shared__ u32 sA1[8][16 * 68];    // per-warp silu(cji) tile, tf32
    __shared__ u32 sA2[8][16 * 36];    // per-warp silu(c1) tile, tf32
    int tid = threadIdx.x;
    for (int idx = tid; idx < 32 * 64; idx += 256) {
        int n = idx >> 6, k = idx & 63;
        sW2[n * 68 + k] = to_tf32(W2[idx]);
    }
    for (int idx = tid; idx < 64 * 32; idx += 256) {
        int n = idx >> 5, k = idx & 31;
        sW3[n * 36 + k] = to_tf32(W3[idx]);
    }
    __syncthreads();

    int w = tid >> 5, lane = tid & 31;
    int gq = lane >> 2, tq = lane & 3;            // groupID, tid-in-group
    long row0 = (long)blockIdx.x * 128 + w * 16;  // this warp's first row
    u32* A1 = sA1[w];
    u32* A2 = sA2[w];

    // stage 16 rows of silu(cji) as tf32 (coalesced float4 per warp)
    for (int i = lane; i < 256; i += 32) {        // 256 float4 = 16 rows x 64
        int rl = i >> 4, c4 = i & 15;
        long rg = row0 + rl;
        uint4 v = make_uint4(0u, 0u, 0u, 0u);
        if (rg < R_TOT) {
            float4 f = *(const float4*)(cji + rg * 64 + c4 * 4);
            v.x = to_tf32(silu(f.x)); v.y = to_tf32(silu(f.y));
            v.z = to_tf32(silu(f.z)); v.w = to_tf32(silu(f.w));
        }
        *(uint4*)&A1[rl * 68 + c4 * 4] = v;
    }
    __syncwarp();

    // GEMM1: C1(16x32) = A1(16x64) @ W2^T
    float c1[4][4];
#pragma unroll
    for (int nt = 0; nt < 4; nt++)
#pragma unroll
        for (int j = 0; j < 4; j++) c1[nt][j] = 0.f;
#pragma unroll
    for (int k0 = 0; k0 < 64; k0 += 8) {
        u32 a0 = A1[gq * 68 + k0 + tq];
        u32 a1 = A1[(gq + 8) * 68 + k0 + tq];
        u32 a2 = A1[gq * 68 + k0 + tq + 4];
        u32 a3 = A1[(gq + 8) * 68 + k0 + tq + 4];
#pragma unroll
        for (int nt = 0; nt < 4; nt++) {
            u32 b0 = sW2[(nt * 8 + gq) * 68 + k0 + tq];
            u32 b1 = sW2[(nt * 8 + gq) * 68 + k0 + tq + 4];
            mma_tf32(c1[nt][0], c1[nt][1], c1[nt][2], c1[nt][3], a0, a1, a2, a3, b0, b1);
        }
    }
    // silu -> A2 (tf32). C layout: c0,c1 at (gq, 2tq(+1)); c2,c3 at (gq+8, ...)
#pragma unroll
    for (int nt = 0; nt < 4; nt++) {
        A2[gq * 36 + nt * 8 + 2 * tq]           = to_tf32(silu(c1[nt][0]));
        A2[gq * 36 + nt * 8 + 2 * tq + 1]       = to_tf32(silu(c1[nt][1]));
        A2[(gq + 8) * 36 + nt * 8 + 2 * tq]     = to_tf32(silu(c1[nt][2]));
        A2[(gq + 8) * 36 + nt * 8 + 2 * tq + 1] = to_tf32(silu(c1[nt][3]));
    }
    __syncwarp();

    // GEMM2: C2(16x64) = A2(16x32) @ W3^T
    float c2[8][4];
#pragma unroll
    for (int nt = 0; nt < 8; nt++)
#pragma unroll
        for (int j = 0; j < 4; j++) c2[nt][j] = 0.f;
#pragma unroll
    for (int k0 = 0; k0 < 32; k0 += 8) {
        u32 a0 = A2[gq * 36 + k0 + tq];
        u32 a1 = A2[(gq + 8) * 36 + k0 + tq];
        u32 a2 = A2[gq * 36 + k0 + tq + 4];
        u32 a3 = A2[(gq + 8) * 36 + k0 + tq + 4];
#pragma unroll
        for (int nt = 0; nt < 8; nt++) {
            u32 b0 = sW3[(nt * 8 + gq) * 36 + k0 + tq];
            u32 b1 = sW3[(nt * 8 + gq) * 36 + k0 + tq + 4];
            mma_tf32(c2[nt][0], c2[nt][1], c2[nt][2], c2[nt][3], a0, a1, a2, a3, b0, b1);
        }
    }

    // epilogue. rows: rA = row0+gq, rB = row0+gq+8
    long rA = row0 + gq, rB = row0 + gq + 8;
    // cji_c raw: n-tiles 0..3 (cols 0..31)
    if (rA < R_TOT) {
#pragma unroll
        for (int nt = 0; nt < 4; nt++) {
            float2 v = make_float2(c2[nt][0], c2[nt][1]);
            *(float2*)&g_cji_c[rA * 32 + nt * 8 + 2 * tq] = v;
        }
    }
    if (rB < R_TOT) {
#pragma unroll
        for (int nt = 0; nt < 4; nt++) {
            float2 v = make_float2(c2[nt][2], c2[nt][3]);
            *(float2*)&g_cji_c[rB * 32 + nt * 8 + 2 * tq] = v;
        }
    }
    // ckj: n-tiles 4..7 (cols 32..63) with per-row l2norm (quad reduction)
    float sa = 0.f, sb = 0.f;
#pragma unroll
    for (int nt = 4; nt < 8; nt++) {
        sa = fmaf(c2[nt][0], c2[nt][0], fmaf(c2[nt][1], c2[nt][1], sa));
        sb = fmaf(c2[nt][2], c2[nt][2], fmaf(c2[nt][3], c2[nt][3], sb));
    }
    sa += __shfl_xor_sync(0xffffffffu, sa, 1);
    sa += __shfl_xor_sync(0xffffffffu, sa, 2);
    sb += __shfl_xor_sync(0xffffffffu, sb, 1);
    sb += __shfl_xor_sync(0xffffffffu, sb, 2);
    float ia = 1.f / fmaxf(sqrtf(sa), 1e-12f);
    float ib = 1.f / fmaxf(sqrtf(sb), 1e-12f);
    if (rA < R_TOT) {
#pragma unroll
        for (int nt = 4; nt < 8; nt++) {
            float2 v = make_float2(c2[nt][0] * ia, c2[nt][1] * ia);
            *(float2*)&g_ckj_n[rA * 32 + (nt - 4) * 8 + 2 * tq] = v;
        }
    }
    if (rB < R_TOT) {
#pragma unroll
        for (int nt = 4; nt < 8; nt++) {
            float2 v = make_float2(c2[nt][2] * ib, c2[nt][3] * ib);
            *(float2*)&g_ckj_n[rB * 32 + (nt - 4) * 8 + 2 * tq] = v;
        }
    }
}

// ---------------- K3: triplets -> edge aggregation --------------------------
__global__ void __launch_bounds__(256) k3_tri(const float* __restrict__ shb,
                                              const int* __restrict__ e_kj,
                                              const int* __restrict__ e_ji,
                                              const int* __restrict__ t_k) {
    int w = threadIdx.x >> 5, lane = threadIdx.x & 31;
    int t = blockIdx.x * 8 + w;
    if (t >= NT) return;
    int kj = e_kj[t], ji = e_ji[t], kn = t_k[t];
    float acc = 0.f;
#pragma unroll
    for (int d = 0; d < NORB; d++) {
        float cf = __ldg(&g_rbw[kj * NORB + d]) * __ldg(&shb[t * NORB + d]);
        acc = fmaf(cf, __ldg(&g_ckj_n[((size_t)kj * NORB + d) * CD + lane]), acc);
    }
    float s = warp_sum(acc * acc);
    float inv = 1.f / fmaxf(sqrtf(s), 1e-12f);
    float tw = acc * inv * sigm(g_h[kn * 64 + 32 + lane]);
    atomicAdd(&g_agg[(size_t)ji * CD + lane], tw);
}

// ---------------- K5: edge finalize (fused tbw + lcao + node MLP + scatter) --
__global__ void __launch_bounds__(256) k5_edge(const float* __restrict__ W4,
                                               const float* __restrict__ b4,
                                               const float* __restrict__ W5,
                                               const float* __restrict__ b5,
                                               const float* __restrict__ W6,
                                               const float* __restrict__ b6,
                                               const int* __restrict__ idx_i,
                                               const int* __restrict__ idx_j) {
    __shared__ __align__(16) float sW4[32 * 36];
    __shared__ __align__(16) float sW5[32 * 68];
    __shared__ __align__(16) float sW6[32 * 36];
    __shared__ __align__(16) float sag[8][32];
    __shared__ __align__(16) float su[8][64];
    __shared__ __align__(16) float sn[8][32];
    int tid = threadIdx.x;
    for (int idx = tid; idx < 32 * 32; idx += 256) {
        int c = idx / 32, k = idx % 32;
        sW4[c * 36 + k] = W4[idx];
        sW6[c * 36 + k] = W6[idx];
    }
    for (int idx = tid; idx < 32 * 64; idx += 256) {
        int c = idx / 64, k = idx % 64;
        sW5[c * 68 + k] = W5[idx];
    }
    __syncthreads();
    int w = tid >> 5, lane = tid & 31;
    int e = blockIdx.x * 8 + w;
    if (e >= NE) return;

    sag[w][lane] = silu(g_agg[(size_t)e * CD + lane]);
    __syncwarp();
    u64 t2 = 0ull;
#pragma unroll
    for (int k4 = 0; k4 < 8; k4++) {
        ulonglong2 wv = *(const ulonglong2*)&sW4[lane * 36 + k4 * 4];
        ulonglong2 av = *(const ulonglong2*)&sag[w][k4 * 4];
        fma2(t2, av.x, wv.x);
        fma2(t2, av.y, wv.y);
    }
    float tb = 1.f + b4[lane] + unp_sum(t2);

    float v[NORB];
    size_t base = (size_t)e * (NORB * CD);
#pragma unroll
    for (int d = 0; d < NORB; d++) v[d] = g_cji_c[base + d * 32 + lane] * tb;
    float lc = 0.f;
#pragma unroll
    for (int d = 0; d < NORB; d++) {
        float s = warp_sum(v[d] * v[d]);
        float inv = 1.f / fmaxf(sqrtf(s), 1e-12f);
        lc = fmaf(__ldg(&g_rbw[e * NORB + d]), v[d] * inv, lc);
    }
    float s = warp_sum(lc * lc);
    lc *= 1.f / fmaxf(sqrtf(s), 1e-12f);

    int ni = idx_i[e], nj = idx_j[e];
    su[w][lane] = silu(g_h[ni * 64 + lane]);
    su[w][lane + 32] = silu(g_h[nj * 64 + lane]);
    __syncwarp();
    u64 a2 = 0ull;
#pragma unroll
    for (int k4 = 0; k4 < 16; k4++) {
        ulonglong2 wv = *(const ulonglong2*)&sW5[lane * 68 + k4 * 4];
        ulonglong2 av = *(const ulonglong2*)&su[w][k4 * 4];
        fma2(a2, av.x, wv.x);
        fma2(a2, av.y, wv.y);
    }
    sn[w][lane] = silu(b5[lane] + unp_sum(a2));
    __syncwarp();
    u64 a3 = 0ull;
#pragma unroll
    for (int k4 = 0; k4 < 8; k4++) {
        ulonglong2 wv = *(const ulonglong2*)&sW6[lane * 36 + k4 * 4];
        ulonglong2 av = *(const ulonglong2*)&sn[w][k4 * 4];
        fma2(a3, av.x, wv.x);
        fma2(a3, av.y, wv.y);
    }
    float nf = b6[lane] + unp_sum(a3);
    atomicAdd(&g_acc[ni * CD + lane], lc * nf);
}

// ---------------- K6: out = x + acc @ W7^T ----------------------------------
__global__ void __launch_bounds__(256) k6_out(const float* __restrict__ x,
                                              const float* __restrict__ W7,
                                              float* __restrict__ out) {
    __shared__ float sW[32 * 128];
    __shared__ float sa[2][32];
    int tid = threadIdx.x;
    for (int idx = tid; idx < 128 * 32; idx += 256) {
        int hc = idx / 32, c = idx % 32;
        sW[c * 128 + hc] = W7[idx];
    }
    int n0 = blockIdx.x * 2;
    if (tid < 64) {
        int r = tid >> 5, c = tid & 31;
        int n = n0 + r;
        if (n < NN) sa[r][c] = g_acc[n * 32 + c];
    }
    __syncthreads();
    int r = tid >> 7, hc = tid & 127;
    int n = n0 + r;
    if (n >= NN) return;
    float acc = x[n * 128 + hc];
#pragma unroll
    for (int c = 0; c < 32; c++) acc = fmaf(sa[r][c], sW[c * 128 + hc], acc);
    out[n * 128 + hc] = acc;
}

// ---------------- host launcher ---------------------------------------------
extern "C" void kernel_launch(void* const* d_in, const int* in_sizes, int n_in,
                              void* d_out, int out_size) {
    int o_ii, o_ij, o_tk, o_ekj, o_eji;
    int o_W1, o_b1, o_W2, o_W3, o_W4, o_b4, o_W5, o_b5, o_W6, o_b6, o_W7;
    if (in_sizes[5] == NE) { // dict order: idx_i at slot 5
        o_ii = 5; o_ij = 6; o_tk = 7; o_ekj = 8; o_eji = 9;
        o_W1 = 10; o_b1 = 11; o_W2 = 12; o_W3 = 13; o_W4 = 14; o_b4 = 15;
        o_W5 = 16; o_b5 = 17; o_W6 = 18; o_b6 = 19; o_W7 = 20;
    } else {                 // signature order: W1 at slot 5
        o_W1 = 5; o_b1 = 6; o_W2 = 7; o_W3 = 8; o_W4 = 9; o_b4 = 10;
        o_W5 = 11; o_b5 = 12; o_W6 = 13; o_b6 = 14; o_W7 = 15;
        o_ii = 16; o_ij = 17; o_tk = 18; o_ekj = 19; o_eji = 20;
    }
    const float* x   = (const float*)d_in[0];
    const float* cji = (const float*)d_in[1];
    const float* cw  = (const float*)d_in[2];
    const float* rb  = (const float*)d_in[3];
    const float* shb = (const float*)d_in[4];
    const int* ii  = (const int*)d_in[o_ii];
    const int* ij  = (const int*)d_in[o_ij];
    const int* tk  = (const int*)d_in[o_tk];
    const int* ekj = (const int*)d_in[o_ekj];
    const int* eji = (const int*)d_in[o_eji];
    const float* W1 = (const float*)d_in[o_W1];
    const float* b1 = (const float*)d_in[o_b1];
    const float* W2 = (const float*)d_in[o_W2];
    const float* W3 = (const float*)d_in[o_W3];
    const float* W4 = (const float*)d_in[o_W4];
    const float* b4 = (const float*)d_in[o_b4];
    const float* W5 = (const float*)d_in[o_W5];
    const float* b5 = (const float*)d_in[o_b5];
    const float* W6 = (const float*)d_in[o_W6];
    const float* b6 = (const float*)d_in[o_b6];
    const float* W7 = (const float*)d_in[o_W7];
    float* out = (float*)d_out;

    k0_init<<<(NE * CD + 255) / 256, 256>>>(rb, cw);
    k1_node<<<(NN + 3) / 4, 256>>>(x, W1, b1);
    k2_mma<<<(R_TOT + 127) / 128, 256>>>(cji, W2, W3);
    k3_tri<<<(NT + 7) / 8, 256>>>(shb, ekj, eji, tk);
    k5_edge<<<(NE + 7) / 8, 256>>>(W4, b4, W5, b5, W6, b6, ii, ij);
    k6_out<<<(NN + 1) / 2, 256>>>(x, W7, out);
}

// round 6
// speedup vs baseline: 1.9033x; 1.0218x over previous
#include <cuda_runtime.h>
#include <cuda_fp16.h>
#include <math.h>

#define NN 10000
#define NE 200000
#define NT 400000
#define NORB 9
#define HD 128
#define CFD 64
#define CD 32
#define R_TOT (NE * NORB)   // 1,800,000 flattened (edge,orb) rows

typedef unsigned long long u64;
typedef unsigned int u32;

// ---------------- scratch (device globals; no allocation allowed) ----------
__device__ float g_h[NN * 64];                     // node MLP out: xh=[0:32), xk=[32:64)
__device__ __half g_cji_c[(size_t)NE * NORB * CD]; // 115.2 MB (fp16)
__device__ __half g_ckj_n[(size_t)NE * NORB * CD]; // 115.2 MB (fp16, pre-normalized)
__device__ float g_rbw[NE * NORB];
__device__ float g_agg[(size_t)NE * CD];
__device__ float g_acc[NN * CD];

__device__ __forceinline__ float sigm(float x) { return 1.f / (1.f + __expf(-x)); }
__device__ __forceinline__ float silu(float x) { return x * sigm(x); }

__device__ __forceinline__ float warp_sum(float s) {
#pragma unroll
    for (int off = 16; off; off >>= 1) s += __shfl_xor_sync(0xffffffffu, s, off);
    return s;
}

// ---- packed fp32x2 FFMA2 (k5) ----------------------------------------------
__device__ __forceinline__ void fma2(u64& d, u64 a, u64 b) {
    asm("fma.rn.f32x2 %0,%1,%2,%0;" : "+l"(d) : "l"(a), "l"(b));
}
__device__ __forceinline__ float unp_sum(u64 v) {
    float x, y; asm("mov.b64 {%0,%1},%2;" : "=f"(x), "=f"(y) : "l"(v)); return x + y;
}

// ---- tf32 helpers -----------------------------------------------------------
__device__ __forceinline__ u32 to_tf32(float f) {
    u32 r; asm("cvt.rna.tf32.f32 %0,%1;" : "=r"(r) : "f"(f)); return r;
}
__device__ __forceinline__ void mma_tf32(float& c0, float& c1, float& c2, float& c3,
                                         u32 a0, u32 a1, u32 a2, u32 a3,
                                         u32 b0, u32 b1) {
    asm("mma.sync.aligned.m16n8k8.row.col.f32.tf32.tf32.f32 "
        "{%0,%1,%2,%3},{%4,%5,%6,%7},{%8,%9},{%0,%1,%2,%3};"
        : "+f"(c0), "+f"(c1), "+f"(c2), "+f"(c3)
        : "r"(a0), "r"(a1), "r"(a2), "r"(a3), "r"(b0), "r"(b1));
}

// ---------------- K0: zero accumulators + rb_w = rb * cutoff_w -------------
__global__ void k0_init(const float* __restrict__ rb, const float* __restrict__ cw) {
    int i = blockIdx.x * blockDim.x + threadIdx.x;
    if (i < NE * CD) g_agg[i] = 0.f;
    if (i < NN * CD) g_acc[i] = 0.f;
    if (i < NE * NORB) g_rbw[i] = rb[i] * cw[i / NORB];
}

// ---------------- K1: h = x @ W1^T + b1 ------------------------------------
__global__ void __launch_bounds__(256) k1_node(const float* __restrict__ x,
                                               const float* __restrict__ W1,
                                               const float* __restrict__ b1) {
    __shared__ float sW[HD * 64];
    __shared__ float sx[4][HD];
    int tid = threadIdx.x;
    for (int idx = tid; idx < 64 * HD; idx += 256) {
        int o = idx / HD, k = idx % HD;
        sW[k * 64 + o] = W1[idx];
    }
    int n0 = blockIdx.x * 4;
#pragma unroll
    for (int r = 0; r < 4; r++) {
        int n = n0 + r;
        if (n < NN)
            for (int k = tid; k < HD; k += 256) sx[r][k] = x[n * HD + k];
    }
    __syncthreads();
    int r = tid / 64, o = tid % 64;
    int n = n0 + r;
    if (n >= NN) return;
    float acc = b1[o];
#pragma unroll 8
    for (int k = 0; k < HD; k++) acc = fmaf(sx[r][k], sW[k * 64 + o], acc);
    g_h[n * 64 + o] = acc;
}

// ---------------- K2: edge coeff MLP on tensor cores (tf32), fp16 outputs ----
__global__ void __launch_bounds__(256) k2_mma(const float* __restrict__ cji,
                                              const float* __restrict__ W2,
                                              const float* __restrict__ W3) {
    __shared__ u32 sW2[32 * 68];       // [n][k] pad 68 (tf32 bits)
    __shared__ u32 sW3[64 * 36];       // [n][k] pad 36
    __shared__ u32 sA1[8][16 * 68];    // per-warp silu(cji) tile, tf32
    __shared__ u32 sA2[8][16 * 36];    // per-warp silu(c1) tile, tf32
    int tid = threadIdx.x;
    for (int idx = tid; idx < 32 * 64; idx += 256) {
        int n = idx >> 6, k = idx & 63;
        sW2[n * 68 + k] = to_tf32(W2[idx]);
    }
    for (int idx = tid; idx < 64 * 32; idx += 256) {
        int n = idx >> 5, k = idx & 31;
        sW3[n * 36 + k] = to_tf32(W3[idx]);
    }
    __syncthreads();

    int w = tid >> 5, lane = tid & 31;
    int gq = lane >> 2, tq = lane & 3;
    long row0 = (long)blockIdx.x * 128 + w * 16;
    u32* A1 = sA1[w];
    u32* A2 = sA2[w];

    // stage 16 rows of silu(cji) as tf32 (coalesced float4 per warp)
    for (int i = lane; i < 256; i += 32) {
        int rl = i >> 4, c4 = i & 15;
        long rg = row0 + rl;
        uint4 v = make_uint4(0u, 0u, 0u, 0u);
        if (rg < R_TOT) {
            float4 f = *(const float4*)(cji + rg * 64 + c4 * 4);
            v.x = to_tf32(silu(f.x)); v.y = to_tf32(silu(f.y));
            v.z = to_tf32(silu(f.z)); v.w = to_tf32(silu(f.w));
        }
        *(uint4*)&A1[rl * 68 + c4 * 4] = v;
    }
    __syncwarp();

    // GEMM1: C1(16x32) = A1(16x64) @ W2^T
    float c1[4][4];
#pragma unroll
    for (int nt = 0; nt < 4; nt++)
#pragma unroll
        for (int j = 0; j < 4; j++) c1[nt][j] = 0.f;
#pragma unroll
    for (int k0 = 0; k0 < 64; k0 += 8) {
        u32 a0 = A1[gq * 68 + k0 + tq];
        u32 a1 = A1[(gq + 8) * 68 + k0 + tq];
        u32 a2 = A1[gq * 68 + k0 + tq + 4];
        u32 a3 = A1[(gq + 8) * 68 + k0 + tq + 4];
#pragma unroll
        for (int nt = 0; nt < 4; nt++) {
            u32 b0 = sW2[(nt * 8 + gq) * 68 + k0 + tq];
            u32 b1 = sW2[(nt * 8 + gq) * 68 + k0 + tq + 4];
            mma_tf32(c1[nt][0], c1[nt][1], c1[nt][2], c1[nt][3], a0, a1, a2, a3, b0, b1);
        }
    }
#pragma unroll
    for (int nt = 0; nt < 4; nt++) {
        A2[gq * 36 + nt * 8 + 2 * tq]           = to_tf32(silu(c1[nt][0]));
        A2[gq * 36 + nt * 8 + 2 * tq + 1]       = to_tf32(silu(c1[nt][1]));
        A2[(gq + 8) * 36 + nt * 8 + 2 * tq]     = to_tf32(silu(c1[nt][2]));
        A2[(gq + 8) * 36 + nt * 8 + 2 * tq + 1] = to_tf32(silu(c1[nt][3]));
    }
    __syncwarp();

    // GEMM2: C2(16x64) = A2(16x32) @ W3^T
    float c2[8][4];
#pragma unroll
    for (int nt = 0; nt < 8; nt++)
#pragma unroll
        for (int j = 0; j < 4; j++) c2[nt][j] = 0.f;
#pragma unroll
    for (int k0 = 0; k0 < 32; k0 += 8) {
        u32 a0 = A2[gq * 36 + k0 + tq];
        u32 a1 = A2[(gq + 8) * 36 + k0 + tq];
        u32 a2 = A2[gq * 36 + k0 + tq + 4];
        u32 a3 = A2[(gq + 8) * 36 + k0 + tq + 4];
#pragma unroll
        for (int nt = 0; nt < 8; nt++) {
            u32 b0 = sW3[(nt * 8 + gq) * 36 + k0 + tq];
            u32 b1 = sW3[(nt * 8 + gq) * 36 + k0 + tq + 4];
            mma_tf32(c2[nt][0], c2[nt][1], c2[nt][2], c2[nt][3], a0, a1, a2, a3, b0, b1);
        }
    }

    // epilogue. rows: rA = row0+gq, rB = row0+gq+8. fp16 stores (half2, 4B aligned)
    long rA = row0 + gq, rB = row0 + gq + 8;
    if (rA < R_TOT) {
#pragma unroll
        for (int nt = 0; nt < 4; nt++)
            *(__half2*)&g_cji_c[rA * 32 + nt * 8 + 2 * tq] = __floats2half2_rn(c2[nt][0], c2[nt][1]);
    }
    if (rB < R_TOT) {
#pragma unroll
        for (int nt = 0; nt < 4; nt++)
            *(__half2*)&g_cji_c[rB * 32 + nt * 8 + 2 * tq] = __floats2half2_rn(c2[nt][2], c2[nt][3]);
    }
    // ckj: n-tiles 4..7 (cols 32..63), per-row l2norm in fp32, then fp16
    float sa = 0.f, sb = 0.f;
#pragma unroll
    for (int nt = 4; nt < 8; nt++) {
        sa = fmaf(c2[nt][0], c2[nt][0], fmaf(c2[nt][1], c2[nt][1], sa));
        sb = fmaf(c2[nt][2], c2[nt][2], fmaf(c2[nt][3], c2[nt][3], sb));
    }
    sa += __shfl_xor_sync(0xffffffffu, sa, 1);
    sa += __shfl_xor_sync(0xffffffffu, sa, 2);
    sb += __shfl_xor_sync(0xffffffffu, sb, 1);
    sb += __shfl_xor_sync(0xffffffffu, sb, 2);
    float ia = 1.f / fmaxf(sqrtf(sa), 1e-12f);
    float ib = 1.f / fmaxf(sqrtf(sb), 1e-12f);
    if (rA < R_TOT) {
#pragma unroll
        for (int nt = 4; nt < 8; nt++)
            *(__half2*)&g_ckj_n[rA * 32 + (nt - 4) * 8 + 2 * tq] =
                __floats2half2_rn(c2[nt][0] * ia, c2[nt][1] * ia);
    }
    if (rB < R_TOT) {
#pragma unroll
        for (int nt = 4; nt < 8; nt++)
            *(__half2*)&g_ckj_n[rB * 32 + (nt - 4) * 8 + 2 * tq] =
                __floats2half2_rn(c2[nt][2] * ib, c2[nt][3] * ib);
    }
}

// ---------------- K3: triplets -> edge aggregation (fp16 gather) -------------
__global__ void __launch_bounds__(256) k3_tri(const float* __restrict__ shb,
                                              const int* __restrict__ e_kj,
                                              const int* __restrict__ e_ji,
                                              const int* __restrict__ t_k) {
    int w = threadIdx.x >> 5, lane = threadIdx.x & 31;
    int t = blockIdx.x * 8 + w;
    if (t >= NT) return;
    int kj = e_kj[t], ji = e_ji[t], kn = t_k[t];
    float acc = 0.f;
#pragma unroll
    for (int d = 0; d < NORB; d++) {
        float cf = __ldg(&g_rbw[kj * NORB + d]) * __ldg(&shb[t * NORB + d]);
        float ck = __half2float(__ldg(&g_ckj_n[((size_t)kj * NORB + d) * CD + lane]));
        acc = fmaf(cf, ck, acc);
    }
    float s = warp_sum(acc * acc);
    float inv = 1.f / fmaxf(sqrtf(s), 1e-12f);
    float tw = acc * inv * sigm(g_h[kn * 64 + 32 + lane]);
    atomicAdd(&g_agg[(size_t)ji * CD + lane], tw);
}

// ---------------- K5: edge finalize (fused tbw + lcao + node MLP + scatter) --
__global__ void __launch_bounds__(256) k5_edge(const float* __restrict__ W4,
                                               const float* __restrict__ b4,
                                               const float* __restrict__ W5,
                                               const float* __restrict__ b5,
                                               const float* __restrict__ W6,
                                               const float* __restrict__ b6,
                                               const int* __restrict__ idx_i,
                                               const int* __restrict__ idx_j) {
    __shared__ __align__(16) float sW4[32 * 36];
    __shared__ __align__(16) float sW5[32 * 68];
    __shared__ __align__(16) float sW6[32 * 36];
    __shared__ __align__(16) float sag[8][32];
    __shared__ __align__(16) float su[8][64];
    __shared__ __align__(16) float sn[8][32];
    int tid = threadIdx.x;
    for (int idx = tid; idx < 32 * 32; idx += 256) {
        int c = idx / 32, k = idx % 32;
        sW4[c * 36 + k] = W4[idx];
        sW6[c * 36 + k] = W6[idx];
    }
    for (int idx = tid; idx < 32 * 64; idx += 256) {
        int c = idx / 64, k = idx % 64;
        sW5[c * 68 + k] = W5[idx];
    }
    __syncthreads();
    int w = tid >> 5, lane = tid & 31;
    int e = blockIdx.x * 8 + w;
    if (e >= NE) return;

    sag[w][lane] = silu(g_agg[(size_t)e * CD + lane]);
    __syncwarp();
    u64 t2 = 0ull;
#pragma unroll
    for (int k4 = 0; k4 < 8; k4++) {
        ulonglong2 wv = *(const ulonglong2*)&sW4[lane * 36 + k4 * 4];
        ulonglong2 av = *(const ulonglong2*)&sag[w][k4 * 4];
        fma2(t2, av.x, wv.x);
        fma2(t2, av.y, wv.y);
    }
    float tb = 1.f + b4[lane] + unp_sum(t2);

    float v[NORB];
    size_t base = (size_t)e * (NORB * CD);
#pragma unroll
    for (int d = 0; d < NORB; d++)
        v[d] = __half2float(__ldg(&g_cji_c[base + d * 32 + lane])) * tb;
    float lc = 0.f;
#pragma unroll
    for (int d = 0; d < NORB; d++) {
        float s = warp_sum(v[d] * v[d]);
        float inv = 1.f / fmaxf(sqrtf(s), 1e-12f);
        lc = fmaf(__ldg(&g_rbw[e * NORB + d]), v[d] * inv, lc);
    }
    float s = warp_sum(lc * lc);
    lc *= 1.f / fmaxf(sqrtf(s), 1e-12f);

    int ni = idx_i[e], nj = idx_j[e];
    su[w][lane] = silu(g_h[ni * 64 + lane]);
    su[w][lane + 32] = silu(g_h[nj * 64 + lane]);
    __syncwarp();
    u64 a2 = 0ull;
#pragma unroll
    for (int k4 = 0; k4 < 16; k4++) {
        ulonglong2 wv = *(const ulonglong2*)&sW5[lane * 68 + k4 * 4];
        ulonglong2 av = *(const ulonglong2*)&su[w][k4 * 4];
        fma2(a2, av.x, wv.x);
        fma2(a2, av.y, wv.y);
    }
    sn[w][lane] = silu(b5[lane] + unp_sum(a2));
    __syncwarp();
    u64 a3 = 0ull;
#pragma unroll
    for (int k4 = 0; k4 < 8; k4++) {
        ulonglong2 wv = *(const ulonglong2*)&sW6[lane * 36 + k4 * 4];
        ulonglong2 av = *(const ulonglong2*)&sn[w][k4 * 4];
        fma2(a3, av.x, wv.x);
        fma2(a3, av.y, wv.y);
    }
    float nf = b6[lane] + unp_sum(a3);
    atomicAdd(&g_acc[ni * CD + lane], lc * nf);
}

// ---------------- K6: out = x + acc @ W7^T ----------------------------------
__global__ void __launch_bounds__(256) k6_out(const float* __restrict__ x,
                                              const float* __restrict__ W7,
                                              float* __restrict__ out) {
    __shared__ float sW[32 * 128];
    __shared__ float sa[2][32];
    int tid = threadIdx.x;
    for (int idx = tid; idx < 128 * 32; idx += 256) {
        int hc = idx / 32, c = idx % 32;
        sW[c * 128 + hc] = W7[idx];
    }
    int n0 = blockIdx.x * 2;
    if (tid < 64) {
        int r = tid >> 5, c = tid & 31;
        int n = n0 + r;
        if (n < NN) sa[r][c] = g_acc[n * 32 + c];
    }
    __syncthreads();
    int r = tid >> 7, hc = tid & 127;
    int n = n0 + r;
    if (n >= NN) return;
    float acc = x[n * 128 + hc];
#pragma unroll
    for (int c = 0; c < 32; c++) acc = fmaf(sa[r][c], sW[c * 128 + hc], acc);
    out[n * 128 + hc] = acc;
}

// ---------------- host launcher ---------------------------------------------
extern "C" void kernel_launch(void* const* d_in, const int* in_sizes, int n_in,
                              void* d_out, int out_size) {
    int o_ii, o_ij, o_tk, o_ekj, o_eji;
    int o_W1, o_b1, o_W2, o_W3, o_W4, o_b4, o_W5, o_b5, o_W6, o_b6, o_W7;
    if (in_sizes[5] == NE) { // dict order: idx_i at slot 5
        o_ii = 5; o_ij = 6; o_tk = 7; o_ekj = 8; o_eji = 9;
        o_W1 = 10; o_b1 = 11; o_W2 = 12; o_W3 = 13; o_W4 = 14; o_b4 = 15;
        o_W5 = 16; o_b5 = 17; o_W6 = 18; o_b6 = 19; o_W7 = 20;
    } else {                 // signature order: W1 at slot 5
        o_W1 = 5; o_b1 = 6; o_W2 = 7; o_W3 = 8; o_W4 = 9; o_b4 = 10;
        o_W5 = 11; o_b5 = 12; o_W6 = 13; o_b6 = 14; o_W7 = 15;
        o_ii = 16; o_ij = 17; o_tk = 18; o_ekj = 19; o_eji = 20;
    }
    const float* x   = (const float*)d_in[0];
    const float* cji = (const float*)d_in[1];
    const float* cw  = (const float*)d_in[2];
    const float* rb  = (const float*)d_in[3];
    const float* shb = (const float*)d_in[4];
    const int* ii  = (const int*)d_in[o_ii];
    const int* ij  = (const int*)d_in[o_ij];
    const int* tk  = (const int*)d_in[o_tk];
    const int* ekj = (const int*)d_in[o_ekj];
    const int* eji = (const int*)d_in[o_eji];
    const float* W1 = (const float*)d_in[o_W1];
    const float* b1 = (const float*)d_in[o_b1];
    const float* W2 = (const float*)d_in[o_W2];
    const float* W3 = (const float*)d_in[o_W3];
    const float* W4 = (const float*)d_in[o_W4];
    const float* b4 = (const float*)d_in[o_b4];
    const float* W5 = (const float*)d_in[o_W5];
    const float* b5 = (const float*)d_in[o_b5];
    const float* W6 = (const float*)d_in[o_W6];
    const float* b6 = (const float*)d_in[o_b6];
    const float* W7 = (const float*)d_in[o_W7];
    float* out = (float*)d_out;

    k0_init<<<(NE * CD + 255) / 256, 256>>>(rb, cw);
    k1_node<<<(NN + 3) / 4, 256>>>(x, W1, b1);
    k2_mma<<<(R_TOT + 127) / 128, 256>>>(cji, W2, W3);
    k3_tri<<<(NT + 7) / 8, 256>>>(shb, ekj, eji, tk);
    k5_edge<<<(NE + 7) / 8, 256>>>(W4, b4, W5, b5, W6, b6, ii, ij);
    k6_out<<<(NN + 1) / 2, 256>>>(x, W7, out);
}

// round 7
// speedup vs baseline: 2.0286x; 1.0659x over previous
#include <cuda_runtime.h>
#include <cuda_fp16.h>
#include <math.h>

#define NN 10000
#define NE 200000
#define NT 400000
#define NORB 9
#define HD 128
#define CFD 64
#define CD 32
#define R_TOT (NE * NORB)   // 1,800,000 flattened (edge,orb) rows

typedef unsigned long long u64;
typedef unsigned int u32;

// ---------------- scratch (device globals; no allocation allowed) ----------
__device__ float g_h[NN * 64];                     // [0:32)=silu(xh), [32:64)=sigm(xk)
__device__ __half g_cji_c[(size_t)NE * NORB * CD]; // 115.2 MB (fp16)
__device__ __half g_ckj_n[(size_t)NE * NORB * CD]; // 115.2 MB (fp16, pre-normalized)
__device__ float g_rbw[NE * NORB];
__device__ float g_agg[(size_t)NE * CD];
__device__ float g_nf[(size_t)NE * CD];            // node-feature MLP output
__device__ float g_acc[NN * CD];

__device__ __forceinline__ float sigm(float x) { return 1.f / (1.f + __expf(-x)); }
__device__ __forceinline__ float silu(float x) { return x * sigm(x); }

__device__ __forceinline__ float warp_sum(float s) {
#pragma unroll
    for (int off = 16; off; off >>= 1) s += __shfl_xor_sync(0xffffffffu, s, off);
    return s;
}

// ---- packed fp32x2 FFMA2 (k5b) ---------------------------------------------
__device__ __forceinline__ void fma2(u64& d, u64 a, u64 b) {
    asm("fma.rn.f32x2 %0,%1,%2,%0;" : "+l"(d) : "l"(a), "l"(b));
}
__device__ __forceinline__ float unp_sum(u64 v) {
    float x, y; asm("mov.b64 {%0,%1},%2;" : "=f"(x), "=f"(y) : "l"(v)); return x + y;
}

// ---- tf32 helpers -----------------------------------------------------------
__device__ __forceinline__ u32 to_tf32(float f) {
    u32 r; asm("cvt.rna.tf32.f32 %0,%1;" : "=r"(r) : "f"(f)); return r;
}
__device__ __forceinline__ void mma_tf32(float& c0, float& c1, float& c2, float& c3,
                                         u32 a0, u32 a1, u32 a2, u32 a3,
                                         u32 b0, u32 b1) {
    asm("mma.sync.aligned.m16n8k8.row.col.f32.tf32.tf32.f32 "
        "{%0,%1,%2,%3},{%4,%5,%6,%7},{%8,%9},{%0,%1,%2,%3};"
        : "+f"(c0), "+f"(c1), "+f"(c2), "+f"(c3)
        : "r"(a0), "r"(a1), "r"(a2), "r"(a3), "r"(b0), "r"(b1));
}

// ---------------- K0: zero accumulators + rb_w = rb * cutoff_w -------------
__global__ void k0_init(const float* __restrict__ rb, const float* __restrict__ cw) {
    int i = blockIdx.x * blockDim.x + threadIdx.x;
    if (i < NE * CD) g_agg[i] = 0.f;
    if (i < NN * CD) g_acc[i] = 0.f;
    if (i < NE * NORB) g_rbw[i] = rb[i] * cw[i / NORB];
}

// ---------------- K1: h = x @ W1^T + b1; store silu(xh) / sigm(xk) ----------
__global__ void __launch_bounds__(256) k1_node(const float* __restrict__ x,
                                               const float* __restrict__ W1,
                                               const float* __restrict__ b1) {
    __shared__ float sW[HD * 64];
    __shared__ float sx[4][HD];
    int tid = threadIdx.x;
    for (int idx = tid; idx < 64 * HD; idx += 256) {
        int o = idx / HD, k = idx % HD;
        sW[k * 64 + o] = W1[idx];
    }
    int n0 = blockIdx.x * 4;
#pragma unroll
    for (int r = 0; r < 4; r++) {
        int n = n0 + r;
        if (n < NN)
            for (int k = tid; k < HD; k += 256) sx[r][k] = x[n * HD + k];
    }
    __syncthreads();
    int r = tid / 64, o = tid % 64;
    int n = n0 + r;
    if (n >= NN) return;
    float acc = b1[o];
#pragma unroll 8
    for (int k = 0; k < HD; k++) acc = fmaf(sx[r][k], sW[k * 64 + o], acc);
    g_h[n * 64 + o] = (o < 32) ? silu(acc) : sigm(acc);
}

// ---------------- K2: edge coeff MLP on tensor cores (tf32), fp16 outputs ----
__global__ void __launch_bounds__(256) k2_mma(const float* __restrict__ cji,
                                              const float* __restrict__ W2,
                                              const float* __restrict__ W3) {
    __shared__ u32 sW2[32 * 68];       // [n][k] pad 68 (tf32 bits)
    __shared__ u32 sW3[64 * 36];       // [n][k] pad 36
    __shared__ u32 sA1[8][16 * 68];    // per-warp silu(cji) tile, tf32
    __shared__ u32 sA2[8][16 * 36];    // per-warp silu(c1) tile, tf32
    int tid = threadIdx.x;
    for (int idx = tid; idx < 32 * 64; idx += 256) {
        int n = idx >> 6, k = idx & 63;
        sW2[n * 68 + k] = to_tf32(W2[idx]);
    }
    for (int idx = tid; idx < 64 * 32; idx += 256) {
        int n = idx >> 5, k = idx & 31;
        sW3[n * 36 + k] = to_tf32(W3[idx]);
    }
    __syncthreads();

    int w = tid >> 5, lane = tid & 31;
    int gq = lane >> 2, tq = lane & 3;
    long row0 = (long)blockIdx.x * 128 + w * 16;
    u32* A1 = sA1[w];
    u32* A2 = sA2[w];

    for (int i = lane; i < 256; i += 32) {
        int rl = i >> 4, c4 = i & 15;
        long rg = row0 + rl;
        uint4 v = make_uint4(0u, 0u, 0u, 0u);
        if (rg < R_TOT) {
            float4 f = *(const float4*)(cji + rg * 64 + c4 * 4);
            v.x = to_tf32(silu(f.x)); v.y = to_tf32(silu(f.y));
            v.z = to_tf32(silu(f.z)); v.w = to_tf32(silu(f.w));
        }
        *(uint4*)&A1[rl * 68 + c4 * 4] = v;
    }
    __syncwarp();

    float c1[4][4];
#pragma unroll
    for (int nt = 0; nt < 4; nt++)
#pragma unroll
        for (int j = 0; j < 4; j++) c1[nt][j] = 0.f;
#pragma unroll
    for (int k0 = 0; k0 < 64; k0 += 8) {
        u32 a0 = A1[gq * 68 + k0 + tq];
        u32 a1 = A1[(gq + 8) * 68 + k0 + tq];
        u32 a2 = A1[gq * 68 + k0 + tq + 4];
        u32 a3 = A1[(gq + 8) * 68 + k0 + tq + 4];
#pragma unroll
        for (int nt = 0; nt < 4; nt++) {
            u32 b0 = sW2[(nt * 8 + gq) * 68 + k0 + tq];
            u32 b1 = sW2[(nt * 8 + gq) * 68 + k0 + tq + 4];
            mma_tf32(c1[nt][0], c1[nt][1], c1[nt][2], c1[nt][3], a0, a1, a2, a3, b0, b1);
        }
    }
#pragma unroll
    for (int nt = 0; nt < 4; nt++) {
        A2[gq * 36 + nt * 8 + 2 * tq]           = to_tf32(silu(c1[nt][0]));
        A2[gq * 36 + nt * 8 + 2 * tq + 1]       = to_tf32(silu(c1[nt][1]));
        A2[(gq + 8) * 36 + nt * 8 + 2 * tq]     = to_tf32(silu(c1[nt][2]));
        A2[(gq + 8) * 36 + nt * 8 + 2 * tq + 1] = to_tf32(silu(c1[nt][3]));
    }
    __syncwarp();

    float c2[8][4];
#pragma unroll
    for (int nt = 0; nt < 8; nt++)
#pragma unroll
        for (int j = 0; j < 4; j++) c2[nt][j] = 0.f;
#pragma unroll
    for (int k0 = 0; k0 < 32; k0 += 8) {
        u32 a0 = A2[gq * 36 + k0 + tq];
        u32 a1 = A2[(gq + 8) * 36 + k0 + tq];
        u32 a2 = A2[gq * 36 + k0 + tq + 4];
        u32 a3 = A2[(gq + 8) * 36 + k0 + tq + 4];
#pragma unroll
        for (int nt = 0; nt < 8; nt++) {
            u32 b0 = sW3[(nt * 8 + gq) * 36 + k0 + tq];
            u32 b1 = sW3[(nt * 8 + gq) * 36 + k0 + tq + 4];
            mma_tf32(c2[nt][0], c2[nt][1], c2[nt][2], c2[nt][3], a0, a1, a2, a3, b0, b1);
        }
    }

    long rA = row0 + gq, rB = row0 + gq + 8;
    if (rA < R_TOT) {
#pragma unroll
        for (int nt = 0; nt < 4; nt++)
            *(__half2*)&g_cji_c[rA * 32 + nt * 8 + 2 * tq] = __floats2half2_rn(c2[nt][0], c2[nt][1]);
    }
    if (rB < R_TOT) {
#pragma unroll
        for (int nt = 0; nt < 4; nt++)
            *(__half2*)&g_cji_c[rB * 32 + nt * 8 + 2 * tq] = __floats2half2_rn(c2[nt][2], c2[nt][3]);
    }
    float sa = 0.f, sb = 0.f;
#pragma unroll
    for (int nt = 4; nt < 8; nt++) {
        sa = fmaf(c2[nt][0], c2[nt][0], fmaf(c2[nt][1], c2[nt][1], sa));
        sb = fmaf(c2[nt][2], c2[nt][2], fmaf(c2[nt][3], c2[nt][3], sb));
    }
    sa += __shfl_xor_sync(0xffffffffu, sa, 1);
    sa += __shfl_xor_sync(0xffffffffu, sa, 2);
    sb += __shfl_xor_sync(0xffffffffu, sb, 1);
    sb += __shfl_xor_sync(0xffffffffu, sb, 2);
    float ia = 1.f / fmaxf(sqrtf(sa), 1e-12f);
    float ib = 1.f / fmaxf(sqrtf(sb), 1e-12f);
    if (rA < R_TOT) {
#pragma unroll
        for (int nt = 4; nt < 8; nt++)
            *(__half2*)&g_ckj_n[rA * 32 + (nt - 4) * 8 + 2 * tq] =
                __floats2half2_rn(c2[nt][0] * ia, c2[nt][1] * ia);
    }
    if (rB < R_TOT) {
#pragma unroll
        for (int nt = 4; nt < 8; nt++)
            *(__half2*)&g_ckj_n[rB * 32 + (nt - 4) * 8 + 2 * tq] =
                __floats2half2_rn(c2[nt][2] * ib, c2[nt][3] * ib);
    }
}

// ---------------- K5a: nf = (silu-gather -> W5 -> silu -> W6) on tensor cores
__global__ void __launch_bounds__(256) k5a_nf(const float* __restrict__ W5,
                                              const float* __restrict__ b5,
                                              const float* __restrict__ W6,
                                              const float* __restrict__ b6,
                                              const int* __restrict__ idx_i,
                                              const int* __restrict__ idx_j) {
    __shared__ u32 sW5[32 * 68];      // [n][k] pad 68
    __shared__ u32 sW6[32 * 36];      // [n][k] pad 36
    __shared__ float sb5[32], sb6[32];
    __shared__ u32 sA1[8][16 * 68];
    __shared__ u32 sA2[8][16 * 36];
    int tid = threadIdx.x;
    for (int idx = tid; idx < 32 * 64; idx += 256) {
        int n = idx >> 6, k = idx & 63;
        sW5[n * 68 + k] = to_tf32(W5[idx]);
    }
    for (int idx = tid; idx < 32 * 32; idx += 256) {
        int n = idx >> 5, k = idx & 31;
        sW6[n * 36 + k] = to_tf32(W6[idx]);
    }
    if (tid < 32) { sb5[tid] = b5[tid]; sb6[tid] = b6[tid]; }
    __syncthreads();

    int w = tid >> 5, lane = tid & 31;
    int gq = lane >> 2, tq = lane & 3;
    long row0 = (long)blockIdx.x * 128 + w * 16;
    u32* A1 = sA1[w];
    u32* A2 = sA2[w];

    // stage A1: cols 0..31 = silu(xh[ii]) (pre-activated in g_h), 32..63 = silu(xh[ij])
    for (int i = lane; i < 256; i += 32) {
        int rl = i >> 4, c4 = i & 15;
        long e = row0 + rl;
        uint4 v = make_uint4(0u, 0u, 0u, 0u);
        if (e < NE) {
            int n = (c4 < 8) ? __ldg(&idx_i[e]) : __ldg(&idx_j[e]);
            float4 f = *(const float4*)&g_h[n * 64 + (c4 & 7) * 4];
            v.x = to_tf32(f.x); v.y = to_tf32(f.y);
            v.z = to_tf32(f.z); v.w = to_tf32(f.w);
        }
        *(uint4*)&A1[rl * 68 + c4 * 4] = v;
    }
    __syncwarp();

    // GEMM1: (16x64)@W5^T -> 16x32
    float c1[4][4];
#pragma unroll
    for (int nt = 0; nt < 4; nt++)
#pragma unroll
        for (int j = 0; j < 4; j++) c1[nt][j] = 0.f;
#pragma unroll
    for (int k0 = 0; k0 < 64; k0 += 8) {
        u32 a0 = A1[gq * 68 + k0 + tq];
        u32 a1 = A1[(gq + 8) * 68 + k0 + tq];
        u32 a2 = A1[gq * 68 + k0 + tq + 4];
        u32 a3 = A1[(gq + 8) * 68 + k0 + tq + 4];
#pragma unroll
        for (int nt = 0; nt < 4; nt++) {
            u32 b0 = sW5[(nt * 8 + gq) * 68 + k0 + tq];
            u32 b1 = sW5[(nt * 8 + gq) * 68 + k0 + tq + 4];
            mma_tf32(c1[nt][0], c1[nt][1], c1[nt][2], c1[nt][3], a0, a1, a2, a3, b0, b1);
        }
    }
#pragma unroll
    for (int nt = 0; nt < 4; nt++) {
        int col = nt * 8 + 2 * tq;
        A2[gq * 36 + col]           = to_tf32(silu(c1[nt][0] + sb5[col]));
        A2[gq * 36 + col + 1]       = to_tf32(silu(c1[nt][1] + sb5[col + 1]));
        A2[(gq + 8) * 36 + col]     = to_tf32(silu(c1[nt][2] + sb5[col]));
        A2[(gq + 8) * 36 + col + 1] = to_tf32(silu(c1[nt][3] + sb5[col + 1]));
    }
    __syncwarp();

    // GEMM2: (16x32)@W6^T -> 16x32
    float c2[4][4];
#pragma unroll
    for (int nt = 0; nt < 4; nt++)
#pragma unroll
        for (int j = 0; j < 4; j++) c2[nt][j] = 0.f;
#pragma unroll
    for (int k0 = 0; k0 < 32; k0 += 8) {
        u32 a0 = A2[gq * 36 + k0 + tq];
        u32 a1 = A2[(gq + 8) * 36 + k0 + tq];
        u32 a2 = A2[gq * 36 + k0 + tq + 4];
        u32 a3 = A2[(gq + 8) * 36 + k0 + tq + 4];
#pragma unroll
        for (int nt = 0; nt < 4; nt++) {
            u32 b0 = sW6[(nt * 8 + gq) * 36 + k0 + tq];
            u32 b1 = sW6[(nt * 8 + gq) * 36 + k0 + tq + 4];
            mma_tf32(c2[nt][0], c2[nt][1], c2[nt][2], c2[nt][3], a0, a1, a2, a3, b0, b1);
        }
    }
    long rA = row0 + gq, rB = row0 + gq + 8;
    if (rA < NE) {
#pragma unroll
        for (int nt = 0; nt < 4; nt++) {
            int col = nt * 8 + 2 * tq;
            *(float2*)&g_nf[rA * 32 + col] =
                make_float2(c2[nt][0] + sb6[col], c2[nt][1] + sb6[col + 1]);
        }
    }
    if (rB < NE) {
#pragma unroll
        for (int nt = 0; nt < 4; nt++) {
            int col = nt * 8 + 2 * tq;
            *(float2*)&g_nf[rB * 32 + col] =
                make_float2(c2[nt][2] + sb6[col], c2[nt][3] + sb6[col + 1]);
        }
    }
}

// ---------------- K3: triplets -> edge aggregation (fp16 gather) -------------
__global__ void __launch_bounds__(256) k3_tri(const float* __restrict__ shb,
                                              const int* __restrict__ e_kj,
                                              const int* __restrict__ e_ji,
                                              const int* __restrict__ t_k) {
    int w = threadIdx.x >> 5, lane = threadIdx.x & 31;
    int t = blockIdx.x * 8 + w;
    if (t >= NT) return;
    int kj = e_kj[t], ji = e_ji[t], kn = t_k[t];
    float acc = 0.f;
#pragma unroll
    for (int d = 0; d < NORB; d++) {
        float cf = __ldg(&g_rbw[kj * NORB + d]) * __ldg(&shb[t * NORB + d]);
        float ck = __half2float(__ldg(&g_ckj_n[((size_t)kj * NORB + d) * CD + lane]));
        acc = fmaf(cf, ck, acc);
    }
    float s = warp_sum(acc * acc);
    float inv = 1.f / fmaxf(sqrtf(s), 1e-12f);
    float tw = acc * inv * g_h[kn * 64 + 32 + lane];  // sigm pre-applied in k1
    atomicAdd(&g_agg[(size_t)ji * CD + lane], tw);
}

// ---------------- K5b: tbw + lcao + multiply nf + scatter --------------------
__global__ void __launch_bounds__(256) k5b_edge(const float* __restrict__ W4,
                                                const float* __restrict__ b4,
                                                const int* __restrict__ idx_i) {
    __shared__ __align__(16) float sW4[32 * 36];
    __shared__ __align__(16) float sag[8][32];
    int tid = threadIdx.x;
    for (int idx = tid; idx < 32 * 32; idx += 256) {
        int c = idx / 32, k = idx % 32;
        sW4[c * 36 + k] = W4[idx];
    }
    __syncthreads();
    int w = tid >> 5, lane = tid & 31;
    int e = blockIdx.x * 8 + w;
    if (e >= NE) return;

    sag[w][lane] = silu(g_agg[(size_t)e * CD + lane]);
    __syncwarp();
    u64 t2 = 0ull;
#pragma unroll
    for (int k4 = 0; k4 < 8; k4++) {
        ulonglong2 wv = *(const ulonglong2*)&sW4[lane * 36 + k4 * 4];
        ulonglong2 av = *(const ulonglong2*)&sag[w][k4 * 4];
        fma2(t2, av.x, wv.x);
        fma2(t2, av.y, wv.y);
    }
    float tb = 1.f + b4[lane] + unp_sum(t2);

    float v[NORB];
    size_t base = (size_t)e * (NORB * CD);
#pragma unroll
    for (int d = 0; d < NORB; d++)
        v[d] = __half2float(__ldg(&g_cji_c[base + d * 32 + lane])) * tb;
    float lc = 0.f;
#pragma unroll
    for (int d = 0; d < NORB; d++) {
        float s = warp_sum(v[d] * v[d]);
        float inv = 1.f / fmaxf(sqrtf(s), 1e-12f);
        lc = fmaf(__ldg(&g_rbw[e * NORB + d]), v[d] * inv, lc);
    }
    float s = warp_sum(lc * lc);
    lc *= 1.f / fmaxf(sqrtf(s), 1e-12f);

    float nf = g_nf[(size_t)e * CD + lane];
    int ni = idx_i[e];
    atomicAdd(&g_acc[ni * CD + lane], lc * nf);
}

// ---------------- K6: out = x + acc @ W7^T ----------------------------------
__global__ void __launch_bounds__(256) k6_out(const float* __restrict__ x,
                                              const float* __restrict__ W7,
                                              float* __restrict__ out) {
    __shared__ float sW[32 * 128];
    __shared__ float sa[2][32];
    int tid = threadIdx.x;
    for (int idx = tid; idx < 128 * 32; idx += 256) {
        int hc = idx / 32, c = idx % 32;
        sW[c * 128 + hc] = W7[idx];
    }
    int n0 = blockIdx.x * 2;
    if (tid < 64) {
        int r = tid >> 5, c = tid & 31;
        int n = n0 + r;
        if (n < NN) sa[r][c] = g_acc[n * 32 + c];
    }
    __syncthreads();
    int r = tid >> 7, hc = tid & 127;
    int n = n0 + r;
    if (n >= NN) return;
    float acc = x[n * 128 + hc];
#pragma unroll
    for (int c = 0; c < 32; c++) acc = fmaf(sa[r][c], sW[c * 128 + hc], acc);
    out[n * 128 + hc] = acc;
}

// ---------------- host launcher ---------------------------------------------
extern "C" void kernel_launch(void* const* d_in, const int* in_sizes, int n_in,
                              void* d_out, int out_size) {
    int o_ii, o_ij, o_tk, o_ekj, o_eji;
    int o_W1, o_b1, o_W2, o_W3, o_W4, o_b4, o_W5, o_b5, o_W6, o_b6, o_W7;
    if (in_sizes[5] == NE) { // dict order: idx_i at slot 5
        o_ii = 5; o_ij = 6; o_tk = 7; o_ekj = 8; o_eji = 9;
        o_W1 = 10; o_b1 = 11; o_W2 = 12; o_W3 = 13; o_W4 = 14; o_b4 = 15;
        o_W5 = 16; o_b5 = 17; o_W6 = 18; o_b6 = 19; o_W7 = 20;
    } else {                 // signature order: W1 at slot 5
        o_W1 = 5; o_b1 = 6; o_W2 = 7; o_W3 = 8; o_W4 = 9; o_b4 = 10;
        o_W5 = 11; o_b5 = 12; o_W6 = 13; o_b6 = 14; o_W7 = 15;
        o_ii = 16; o_ij = 17; o_tk = 18; o_ekj = 19; o_eji = 20;
    }
    const float* x   = (const float*)d_in[0];
    const float* cji = (const float*)d_in[1];
    const float* cw  = (const float*)d_in[2];
    const float* rb  = (const float*)d_in[3];
    const float* shb = (const float*)d_in[4];
    const int* ii  = (const int*)d_in[o_ii];
    const int* ij  = (const int*)d_in[o_ij];
    const int* tk  = (const int*)d_in[o_tk];
    const int* ekj = (const int*)d_in[o_ekj];
    const int* eji = (const int*)d_in[o_eji];
    const float* W1 = (const float*)d_in[o_W1];
    const float* b1 = (const float*)d_in[o_b1];
    const float* W2 = (const float*)d_in[o_W2];
    const float* W3 = (const float*)d_in[o_W3];
    const float* W4 = (const float*)d_in[o_W4];
    const float* b4 = (const float*)d_in[o_b4];
    const float* W5 = (const float*)d_in[o_W5];
    const float* b5 = (const float*)d_in[o_b5];
    const float* W6 = (const float*)d_in[o_W6];
    const float* b6 = (const float*)d_in[o_b6];
    const float* W7 = (const float*)d_in[o_W7];
    float* out = (float*)d_out;

    k0_init<<<(NE * CD + 255) / 256, 256>>>(rb, cw);
    k1_node<<<(NN + 3) / 4, 256>>>(x, W1, b1);
    k2_mma<<<(R_TOT + 127) / 128, 256>>>(cji, W2, W3);
    k5a_nf<<<(NE + 127) / 128, 256>>>(W5, b5, W6, b6, ii, ij);
    k3_tri<<<(NT + 7) / 8, 256>>>(shb, ekj, eji, tk);
    k5b_edge<<<(NE + 7) / 8, 256>>>(W4, b4, ii);
    k6_out<<<(NN + 1) / 2, 256>>>(x, W7, out);
}

// round 8
// speedup vs baseline: 2.2466x; 1.1074x over previous
#include <cuda_runtime.h>
#include <cuda_fp16.h>
#include <math.h>

#define NN 10000
#define NE 200000
#define NT 400000
#define NORB 9
#define HD 128
#define CFD 64
#define CD 32
#define R_TOT (NE * NORB)   // 1,800,000 flattened (edge,orb) rows

typedef unsigned long long u64;
typedef unsigned int u32;

// ---------------- scratch (device globals; no allocation allowed) ----------
__device__ float g_h[NN * 64];                     // [0:32)=silu(xh), [32:64)=sigm(xk)
__device__ __half g_cji_c[(size_t)NE * NORB * CD]; // 115.2 MB (fp16)
__device__ __half g_ckj_n[(size_t)NE * NORB * CD]; // 115.2 MB (fp16, pre-normalized)
__device__ float g_rbw[NE * NORB];
__device__ float g_agg[(size_t)NE * CD];
__device__ float g_nf[(size_t)NE * CD];            // node-feature MLP output
__device__ float g_acc[NN * CD];

__device__ __forceinline__ float sigm(float x) { return 1.f / (1.f + __expf(-x)); }
__device__ __forceinline__ float silu(float x) { return x * sigm(x); }

__device__ __forceinline__ float warp_sum(float s) {
#pragma unroll
    for (int off = 16; off; off >>= 1) s += __shfl_xor_sync(0xffffffffu, s, off);
    return s;
}

// ---- packed fp32x2 FFMA2 (k5b W4 gemm) -------------------------------------
__device__ __forceinline__ void fma2(u64& d, u64 a, u64 b) {
    asm("fma.rn.f32x2 %0,%1,%2,%0;" : "+l"(d) : "l"(a), "l"(b));
}
__device__ __forceinline__ float unp_sum(u64 v) {
    float x, y; asm("mov.b64 {%0,%1},%2;" : "=f"(x), "=f"(y) : "l"(v)); return x + y;
}

// ---- tf32 helpers -----------------------------------------------------------
__device__ __forceinline__ u32 to_tf32(float f) {
    u32 r; asm("cvt.rna.tf32.f32 %0,%1;" : "=r"(r) : "f"(f)); return r;
}
__device__ __forceinline__ void mma_tf32(float& c0, float& c1, float& c2, float& c3,
                                         u32 a0, u32 a1, u32 a2, u32 a3,
                                         u32 b0, u32 b1) {
    asm("mma.sync.aligned.m16n8k8.row.col.f32.tf32.tf32.f32 "
        "{%0,%1,%2,%3},{%4,%5,%6,%7},{%8,%9},{%0,%1,%2,%3};"
        : "+f"(c0), "+f"(c1), "+f"(c2), "+f"(c3)
        : "r"(a0), "r"(a1), "r"(a2), "r"(a3), "r"(b0), "r"(b1));
}

// ---------------- K0: zero accumulators + rb_w = rb * cutoff_w -------------
__global__ void k0_init(const float* __restrict__ rb, const float* __restrict__ cw) {
    int i = blockIdx.x * blockDim.x + threadIdx.x;
    if (i < NE * CD) g_agg[i] = 0.f;
    if (i < NN * CD) g_acc[i] = 0.f;
    if (i < NE * NORB) g_rbw[i] = rb[i] * cw[i / NORB];
}

// ---------------- K1: h = x @ W1^T + b1; store silu(xh) / sigm(xk) ----------
__global__ void __launch_bounds__(256) k1_node(const float* __restrict__ x,
                                               const float* __restrict__ W1,
                                               const float* __restrict__ b1) {
    __shared__ float sW[HD * 64];
    __shared__ float sx[4][HD];
    int tid = threadIdx.x;
    for (int idx = tid; idx < 64 * HD; idx += 256) {
        int o = idx / HD, k = idx % HD;
        sW[k * 64 + o] = W1[idx];
    }
    int n0 = blockIdx.x * 4;
#pragma unroll
    for (int r = 0; r < 4; r++) {
        int n = n0 + r;
        if (n < NN)
            for (int k = tid; k < HD; k += 256) sx[r][k] = x[n * HD + k];
    }
    __syncthreads();
    int r = tid / 64, o = tid % 64;
    int n = n0 + r;
    if (n >= NN) return;
    float acc = b1[o];
#pragma unroll 8
    for (int k = 0; k < HD; k++) acc = fmaf(sx[r][k], sW[k * 64 + o], acc);
    g_h[n * 64 + o] = (o < 32) ? silu(acc) : sigm(acc);
}

// ---------------- K2: edge coeff MLP, tf32 tensor cores, A2 aliased on A1 ----
__global__ void __launch_bounds__(256) k2_mma(const float* __restrict__ cji,
                                              const float* __restrict__ W2,
                                              const float* __restrict__ W3) {
    __shared__ u32 sW2[32 * 68];       // [n][k] pad 68 (tf32 bits)
    __shared__ u32 sW3[64 * 36];       // [n][k] pad 36
    __shared__ u32 sA1[8][16 * 68];    // per-warp tile; A2 overlays same buffer
    int tid = threadIdx.x;
    for (int idx = tid; idx < 32 * 64; idx += 256) {
        int n = idx >> 6, k = idx & 63;
        sW2[n * 68 + k] = to_tf32(W2[idx]);
    }
    for (int idx = tid; idx < 64 * 32; idx += 256) {
        int n = idx >> 5, k = idx & 31;
        sW3[n * 36 + k] = to_tf32(W3[idx]);
    }
    __syncthreads();

    int w = tid >> 5, lane = tid & 31;
    int gq = lane >> 2, tq = lane & 3;
    long row0 = (long)blockIdx.x * 128 + w * 16;
    u32* A1 = sA1[w];
    u32* A2 = sA1[w];   // alias: A1 fully consumed into regs before A2 writes

    for (int i = lane; i < 256; i += 32) {
        int rl = i >> 4, c4 = i & 15;
        long rg = row0 + rl;
        uint4 v = make_uint4(0u, 0u, 0u, 0u);
        if (rg < R_TOT) {
            float4 f = *(const float4*)(cji + rg * 64 + c4 * 4);
            v.x = to_tf32(silu(f.x)); v.y = to_tf32(silu(f.y));
            v.z = to_tf32(silu(f.z)); v.w = to_tf32(silu(f.w));
        }
        *(uint4*)&A1[rl * 68 + c4 * 4] = v;
    }
    __syncwarp();

    float c1[4][4];
#pragma unroll
    for (int nt = 0; nt < 4; nt++)
#pragma unroll
        for (int j = 0; j < 4; j++) c1[nt][j] = 0.f;
#pragma unroll
    for (int k0 = 0; k0 < 64; k0 += 8) {
        u32 a0 = A1[gq * 68 + k0 + tq];
        u32 a1 = A1[(gq + 8) * 68 + k0 + tq];
        u32 a2 = A1[gq * 68 + k0 + tq + 4];
        u32 a3 = A1[(gq + 8) * 68 + k0 + tq + 4];
#pragma unroll
        for (int nt = 0; nt < 4; nt++) {
            u32 b0 = sW2[(nt * 8 + gq) * 68 + k0 + tq];
            u32 b1 = sW2[(nt * 8 + gq) * 68 + k0 + tq + 4];
            mma_tf32(c1[nt][0], c1[nt][1], c1[nt][2], c1[nt][3], a0, a1, a2, a3, b0, b1);
        }
    }
    __syncwarp();
#pragma unroll
    for (int nt = 0; nt < 4; nt++) {
        A2[gq * 36 + nt * 8 + 2 * tq]           = to_tf32(silu(c1[nt][0]));
        A2[gq * 36 + nt * 8 + 2 * tq + 1]       = to_tf32(silu(c1[nt][1]));
        A2[(gq + 8) * 36 + nt * 8 + 2 * tq]     = to_tf32(silu(c1[nt][2]));
        A2[(gq + 8) * 36 + nt * 8 + 2 * tq + 1] = to_tf32(silu(c1[nt][3]));
    }
    __syncwarp();

    float c2[8][4];
#pragma unroll
    for (int nt = 0; nt < 8; nt++)
#pragma unroll
        for (int j = 0; j < 4; j++) c2[nt][j] = 0.f;
#pragma unroll
    for (int k0 = 0; k0 < 32; k0 += 8) {
        u32 a0 = A2[gq * 36 + k0 + tq];
        u32 a1 = A2[(gq + 8) * 36 + k0 + tq];
        u32 a2 = A2[gq * 36 + k0 + tq + 4];
        u32 a3 = A2[(gq + 8) * 36 + k0 + tq + 4];
#pragma unroll
        for (int nt = 0; nt < 8; nt++) {
            u32 b0 = sW3[(nt * 8 + gq) * 36 + k0 + tq];
            u32 b1 = sW3[(nt * 8 + gq) * 36 + k0 + tq + 4];
            mma_tf32(c2[nt][0], c2[nt][1], c2[nt][2], c2[nt][3], a0, a1, a2, a3, b0, b1);
        }
    }

    long rA = row0 + gq, rB = row0 + gq + 8;
    if (rA < R_TOT) {
#pragma unroll
        for (int nt = 0; nt < 4; nt++)
            *(__half2*)&g_cji_c[rA * 32 + nt * 8 + 2 * tq] = __floats2half2_rn(c2[nt][0], c2[nt][1]);
    }
    if (rB < R_TOT) {
#pragma unroll
        for (int nt = 0; nt < 4; nt++)
            *(__half2*)&g_cji_c[rB * 32 + nt * 8 + 2 * tq] = __floats2half2_rn(c2[nt][2], c2[nt][3]);
    }
    float sa = 0.f, sb = 0.f;
#pragma unroll
    for (int nt = 4; nt < 8; nt++) {
        sa = fmaf(c2[nt][0], c2[nt][0], fmaf(c2[nt][1], c2[nt][1], sa));
        sb = fmaf(c2[nt][2], c2[nt][2], fmaf(c2[nt][3], c2[nt][3], sb));
    }
    sa += __shfl_xor_sync(0xffffffffu, sa, 1);
    sa += __shfl_xor_sync(0xffffffffu, sa, 2);
    sb += __shfl_xor_sync(0xffffffffu, sb, 1);
    sb += __shfl_xor_sync(0xffffffffu, sb, 2);
    float ia = 1.f / fmaxf(sqrtf(sa), 1e-12f);
    float ib = 1.f / fmaxf(sqrtf(sb), 1e-12f);
    if (rA < R_TOT) {
#pragma unroll
        for (int nt = 4; nt < 8; nt++)
            *(__half2*)&g_ckj_n[rA * 32 + (nt - 4) * 8 + 2 * tq] =
                __floats2half2_rn(c2[nt][0] * ia, c2[nt][1] * ia);
    }
    if (rB < R_TOT) {
#pragma unroll
        for (int nt = 4; nt < 8; nt++)
            *(__half2*)&g_ckj_n[rB * 32 + (nt - 4) * 8 + 2 * tq] =
                __floats2half2_rn(c2[nt][2] * ib, c2[nt][3] * ib);
    }
}

// ---------------- K5a: nf MLP on tensor cores, A2 aliased on A1 --------------
__global__ void __launch_bounds__(256) k5a_nf(const float* __restrict__ W5,
                                              const float* __restrict__ b5,
                                              const float* __restrict__ W6,
                                              const float* __restrict__ b6,
                                              const int* __restrict__ idx_i,
                                              const int* __restrict__ idx_j) {
    __shared__ u32 sW5[32 * 68];
    __shared__ u32 sW6[32 * 36];
    __shared__ float sb5[32], sb6[32];
    __shared__ u32 sA1[8][16 * 68];   // A2 overlays
    int tid = threadIdx.x;
    for (int idx = tid; idx < 32 * 64; idx += 256) {
        int n = idx >> 6, k = idx & 63;
        sW5[n * 68 + k] = to_tf32(W5[idx]);
    }
    for (int idx = tid; idx < 32 * 32; idx += 256) {
        int n = idx >> 5, k = idx & 31;
        sW6[n * 36 + k] = to_tf32(W6[idx]);
    }
    if (tid < 32) { sb5[tid] = b5[tid]; sb6[tid] = b6[tid]; }
    __syncthreads();

    int w = tid >> 5, lane = tid & 31;
    int gq = lane >> 2, tq = lane & 3;
    long row0 = (long)blockIdx.x * 128 + w * 16;
    u32* A1 = sA1[w];
    u32* A2 = sA1[w];

    for (int i = lane; i < 256; i += 32) {
        int rl = i >> 4, c4 = i & 15;
        long e = row0 + rl;
        uint4 v = make_uint4(0u, 0u, 0u, 0u);
        if (e < NE) {
            int n = (c4 < 8) ? __ldg(&idx_i[e]) : __ldg(&idx_j[e]);
            float4 f = *(const float4*)&g_h[n * 64 + (c4 & 7) * 4];
            v.x = to_tf32(f.x); v.y = to_tf32(f.y);
            v.z = to_tf32(f.z); v.w = to_tf32(f.w);
        }
        *(uint4*)&A1[rl * 68 + c4 * 4] = v;
    }
    __syncwarp();

    float c1[4][4];
#pragma unroll
    for (int nt = 0; nt < 4; nt++)
#pragma unroll
        for (int j = 0; j < 4; j++) c1[nt][j] = 0.f;
#pragma unroll
    for (int k0 = 0; k0 < 64; k0 += 8) {
        u32 a0 = A1[gq * 68 + k0 + tq];
        u32 a1 = A1[(gq + 8) * 68 + k0 + tq];
        u32 a2 = A1[gq * 68 + k0 + tq + 4];
        u32 a3 = A1[(gq + 8) * 68 + k0 + tq + 4];
#pragma unroll
        for (int nt = 0; nt < 4; nt++) {
            u32 b0 = sW5[(nt * 8 + gq) * 68 + k0 + tq];
            u32 b1 = sW5[(nt * 8 + gq) * 68 + k0 + tq + 4];
            mma_tf32(c1[nt][0], c1[nt][1], c1[nt][2], c1[nt][3], a0, a1, a2, a3, b0, b1);
        }
    }
    __syncwarp();
#pragma unroll
    for (int nt = 0; nt < 4; nt++) {
        int col = nt * 8 + 2 * tq;
        A2[gq * 36 + col]           = to_tf32(silu(c1[nt][0] + sb5[col]));
        A2[gq * 36 + col + 1]       = to_tf32(silu(c1[nt][1] + sb5[col + 1]));
        A2[(gq + 8) * 36 + col]     = to_tf32(silu(c1[nt][2] + sb5[col]));
        A2[(gq + 8) * 36 + col + 1] = to_tf32(silu(c1[nt][3] + sb5[col + 1]));
    }
    __syncwarp();

    float c2[4][4];
#pragma unroll
    for (int nt = 0; nt < 4; nt++)
#pragma unroll
        for (int j = 0; j < 4; j++) c2[nt][j] = 0.f;
#pragma unroll
    for (int k0 = 0; k0 < 32; k0 += 8) {
        u32 a0 = A2[gq * 36 + k0 + tq];
        u32 a1 = A2[(gq + 8) * 36 + k0 + tq];
        u32 a2 = A2[gq * 36 + k0 + tq + 4];
        u32 a3 = A2[(gq + 8) * 36 + k0 + tq + 4];
#pragma unroll
        for (int nt = 0; nt < 4; nt++) {
            u32 b0 = sW6[(nt * 8 + gq) * 36 + k0 + tq];
            u32 b1 = sW6[(nt * 8 + gq) * 36 + k0 + tq + 4];
            mma_tf32(c2[nt][0], c2[nt][1], c2[nt][2], c2[nt][3], a0, a1, a2, a3, b0, b1);
        }
    }
    long rA = row0 + gq, rB = row0 + gq + 8;
    if (rA < NE) {
#pragma unroll
        for (int nt = 0; nt < 4; nt++) {
            int col = nt * 8 + 2 * tq;
            *(float2*)&g_nf[rA * 32 + col] =
                make_float2(c2[nt][0] + sb6[col], c2[nt][1] + sb6[col + 1]);
        }
    }
    if (rB < NE) {
#pragma unroll
        for (int nt = 0; nt < 4; nt++) {
            int col = nt * 8 + 2 * tq;
            *(float2*)&g_nf[rB * 32 + col] =
                make_float2(c2[nt][2] + sb6[col], c2[nt][3] + sb6[col + 1]);
        }
    }
}

// ---------------- K3: triplets -> edge aggregation (fp16 gather) -------------
__global__ void __launch_bounds__(256) k3_tri(const float* __restrict__ shb,
                                              const int* __restrict__ e_kj,
                                              const int* __restrict__ e_ji,
                                              const int* __restrict__ t_k) {
    int w = threadIdx.x >> 5, lane = threadIdx.x & 31;
    int t = blockIdx.x * 8 + w;
    if (t >= NT) return;
    int kj = e_kj[t], ji = e_ji[t], kn = t_k[t];
    float acc = 0.f;
#pragma unroll
    for (int d = 0; d < NORB; d++) {
        float cf = __ldg(&g_rbw[kj * NORB + d]) * __ldg(&shb[t * NORB + d]);
        float ck = __half2float(__ldg(&g_ckj_n[((size_t)kj * NORB + d) * CD + lane]));
        acc = fmaf(cf, ck, acc);
    }
    float s = warp_sum(acc * acc);
    float inv = 1.f / fmaxf(sqrtf(s), 1e-12f);
    float tw = acc * inv * g_h[kn * 64 + 32 + lane];  // sigm pre-applied in k1
    atomicAdd(&g_agg[(size_t)ji * CD + lane], tw);
}

// ---------------- K5b: tbw + lcao (batched butterflies) + scatter ------------
__global__ void __launch_bounds__(256) k5b_edge(const float* __restrict__ W4,
                                                const float* __restrict__ b4,
                                                const int* __restrict__ idx_i) {
    __shared__ __align__(16) float sW4[32 * 36];
    __shared__ __align__(16) float sag[8][32];
    int tid = threadIdx.x;
    for (int idx = tid; idx < 32 * 32; idx += 256) {
        int c = idx / 32, k = idx % 32;
        sW4[c * 36 + k] = W4[idx];
    }
    __syncthreads();
    int w = tid >> 5, lane = tid & 31;
    int e = blockIdx.x * 8 + w;
    if (e >= NE) return;

    // tbw = silu(agg) @ W4^T + b4
    sag[w][lane] = silu(g_agg[(size_t)e * CD + lane]);
    __syncwarp();
    u64 t2 = 0ull;
#pragma unroll
    for (int k4 = 0; k4 < 8; k4++) {
        ulonglong2 wv = *(const ulonglong2*)&sW4[lane * 36 + k4 * 4];
        ulonglong2 av = *(const ulonglong2*)&sag[w][k4 * 4];
        fma2(t2, av.x, wv.x);
        fma2(t2, av.y, wv.y);
    }
    float tb = 1.f + b4[lane] + unp_sum(t2);

    // lcao: lc[c] = tb[c] * sum_d (rbw[d]/||cji_c[d,:]*tb||) * cji_c[d][c]
    float vv[NORB], ss[NORB];
    size_t base = (size_t)e * (NORB * CD);
#pragma unroll
    for (int d = 0; d < NORB; d++) {
        vv[d] = __half2float(__ldg(&g_cji_c[base + d * 32 + lane]));
        float t = vv[d] * tb;
        ss[d] = t * t;
    }
    // one batched butterfly over all 9 values: 5 dependency levels total
#pragma unroll
    for (int off = 16; off; off >>= 1) {
#pragma unroll
        for (int d = 0; d < NORB; d++)
            ss[d] += __shfl_xor_sync(0xffffffffu, ss[d], off);
    }
    float lc = 0.f;
#pragma unroll
    for (int d = 0; d < NORB; d++) {
        float inv = 1.f / fmaxf(sqrtf(ss[d]), 1e-12f);
        lc = fmaf(__ldg(&g_rbw[e * NORB + d]) * inv, vv[d], lc);
    }
    lc *= tb;
    float s = warp_sum(lc * lc);
    lc *= 1.f / fmaxf(sqrtf(s), 1e-12f);

    float nf = g_nf[(size_t)e * CD + lane];
    int ni = idx_i[e];
    atomicAdd(&g_acc[ni * CD + lane], lc * nf);
}

// ---------------- K6: out = x + acc @ W7^T ----------------------------------
__global__ void __launch_bounds__(256) k6_out(const float* __restrict__ x,
                                              const float* __restrict__ W7,
                                              float* __restrict__ out) {
    __shared__ float sW[32 * 128];
    __shared__ float sa[2][32];
    int tid = threadIdx.x;
    for (int idx = tid; idx < 128 * 32; idx += 256) {
        int hc = idx / 32, c = idx % 32;
        sW[c * 128 + hc] = W7[idx];
    }
    int n0 = blockIdx.x * 2;
    if (tid < 64) {
        int r = tid >> 5, c = tid & 31;
        int n = n0 + r;
        if (n < NN) sa[r][c] = g_acc[n * 32 + c];
    }
    __syncthreads();
    int r = tid >> 7, hc = tid & 127;
    int n = n0 + r;
    if (n >= NN) return;
    float acc = x[n * 128 + hc];
#pragma unroll
    for (int c = 0; c < 32; c++) acc = fmaf(sa[r][c], sW[c * 128 + hc], acc);
    out[n * 128 + hc] = acc;
}

// ---------------- host launcher ---------------------------------------------
extern "C" void kernel_launch(void* const* d_in, const int* in_sizes, int n_in,
                              void* d_out, int out_size) {
    int o_ii, o_ij, o_tk, o_ekj, o_eji;
    int o_W1, o_b1, o_W2, o_W3, o_W4, o_b4, o_W5, o_b5, o_W6, o_b6, o_W7;
    if (in_sizes[5] == NE) { // dict order: idx_i at slot 5
        o_ii = 5; o_ij = 6; o_tk = 7; o_ekj = 8; o_eji = 9;
        o_W1 = 10; o_b1 = 11; o_W2 = 12; o_W3 = 13; o_W4 = 14; o_b4 = 15;
        o_W5 = 16; o_b5 = 17; o_W6 = 18; o_b6 = 19; o_W7 = 20;
    } else {                 // signature order: W1 at slot 5
        o_W1 = 5; o_b1 = 6; o_W2 = 7; o_W3 = 8; o_W4 = 9; o_b4 = 10;
        o_W5 = 11; o_b5 = 12; o_W6 = 13; o_b6 = 14; o_W7 = 15;
        o_ii = 16; o_ij = 17; o_tk = 18; o_ekj = 19; o_eji = 20;
    }
    const float* x   = (const float*)d_in[0];
    const float* cji = (const float*)d_in[1];
    const float* cw  = (const float*)d_in[2];
    const float* rb  = (const float*)d_in[3];
    const float* shb = (const float*)d_in[4];
    const int* ii  = (const int*)d_in[o_ii];
    const int* ij  = (const int*)d_in[o_ij];
    const int* tk  = (const int*)d_in[o_tk];
    const int* ekj = (const int*)d_in[o_ekj];
    const int* eji = (const int*)d_in[o_eji];
    const float* W1 = (const float*)d_in[o_W1];
    const float* b1 = (const float*)d_in[o_b1];
    const float* W2 = (const float*)d_in[o_W2];
    const float* W3 = (const float*)d_in[o_W3];
    const float* W4 = (const float*)d_in[o_W4];
    const float* b4 = (const float*)d_in[o_b4];
    const float* W5 = (const float*)d_in[o_W5];
    const float* b5 = (const float*)d_in[o_b5];
    const float* W6 = (const float*)d_in[o_W6];
    const float* b6 = (const float*)d_in[o_b6];
    const float* W7 = (const float*)d_in[o_W7];
    float* out = (float*)d_out;

    k0_init<<<(NE * CD + 255) / 256, 256>>>(rb, cw);
    k1_node<<<(NN + 3) / 4, 256>>>(x, W1, b1);
    k2_mma<<<(R_TOT + 127) / 128, 256>>>(cji, W2, W3);
    k5a_nf<<<(NE + 127) / 128, 256>>>(W5, b5, W6, b6, ii, ij);
    k3_tri<<<(NT + 7) / 8, 256>>>(shb, ekj, eji, tk);
    k5b_edge<<<(NE + 7) / 8, 256>>>(W4, b4, ii);
    k6_out<<<(NN + 1) / 2, 256>>>(x, W7, out);
}